// round 13
// baseline (speedup 1.0000x reference)
#include <cuda_runtime.h>
#include <cuda_bf16.h>
#include <float.h>
#include <math.h>

// ---------------- problem constants ----------------
namespace cfg {
constexpr int B_ = 8, G_ = 1025, GP_ = 1024, C_ = 384, H_ = 6, DH_ = 64;
constexpr int NS_ = 6, MSEG_ = 1024, SEG1_ = 1536;      // SEG1 = B*GRID
constexpr int NPT_ = B_ * GP_;                          // 8192 points
constexpr int ROWS_ = B_ * G_;                          // 8200 rows incl cls
constexpr int NSEGT_ = NS_ * SEG1_;                     // 9216

// scratch layout (floats; several regions hold bf16 and use half)
constexpr long O_LN   = 0;                              // bf16
constexpr long O_QKV  = O_LN   + (long)ROWS_ * C_;      // bf16
constexpr long O_ATT  = O_QKV  + (long)ROWS_ * 3 * C_;  // bf16
constexpr long O_X1   = O_ATT  + (long)ROWS_ * C_;
constexpr long O_HFC  = O_X1   + (long)ROWS_ * C_;      // bf16
constexpr long O_XFFN = O_HFC  + (long)ROWS_ * 4 * C_;
constexpr long O_A1   = O_XFFN + (long)ROWS_ * C_;
constexpr long O_X2   = O_A1   + (long)ROWS_ * 48;
constexpr long O_FEAT = O_X2   + (long)ROWS_ * C_;
constexpr long O_LNB  = O_FEAT + (long)NPT_ * C_;       // bf16
constexpr long O_FX   = O_LNB  + (long)NPT_ * C_;
constexpr long O_T3D  = O_FX   + (long)NS_ * NPT_ * C_;
constexpr long O_BN3D = O_T3D  + (long)MSEG_ * C_;
constexpr long O_MEAN3= O_BN3D + (long)MSEG_ * C_;
constexpr long O_RSTD3= O_MEAN3+ C_;
constexpr long O_SUM1 = O_RSTD3+ C_;
constexpr long O_MEAN1= O_SUM1 + (long)NSEGT_ * C_;
constexpr long O_RSTD1= O_MEAN1+ (long)NS_ * C_;
constexpr long O_WATT = O_RSTD1+ (long)NS_ * C_;        // bf16
constexpr long O_BATT = O_WATT + (long)NS_ * C_ * C_ / 2;
constexpr long O_WIN  = O_BATT + (long)NS_ * C_;        // bf16
constexpr long O_WOUT = O_WIN  + (long)3 * C_ * C_ / 2; // bf16
constexpr long O_WFC  = O_WOUT + (long)C_ * C_ / 2;     // bf16
constexpr long O_WPROJ= O_WFC  + (long)4 * C_ * C_ / 2; // bf16
constexpr long O_CNT  = O_WPROJ+ (long)4 * C_ * C_ / 2; // int[NSEGT]
constexpr long O_OFF  = O_CNT  + NSEGT_;                // int[NSEGT]
constexpr long O_CUR  = O_OFF  + NSEGT_;                // int[NSEGT]
constexpr long O_LIST = O_CUR  + NSEGT_;                // int[NS*NPT]
constexpr long TOTAL  = O_LIST + (long)NS_ * NPT_;
}
using namespace cfg;

__device__ __align__(16) float g_scratch[TOTAL];

// ---------------- helpers ----------------
__device__ __forceinline__ unsigned pack_bf16(float lo, float hi) {
    unsigned r;
    asm("cvt.rn.bf16x2.f32 %0, %1, %2;" : "=r"(r) : "f"(hi), "f"(lo));
    return r;
}

__device__ __forceinline__ void mma_bf16(float c[4], const unsigned a[4], const unsigned b[2]) {
    asm volatile(
        "mma.sync.aligned.m16n8k16.row.col.f32.bf16.bf16.f32 "
        "{%0,%1,%2,%3},{%4,%5,%6,%7},{%8,%9},{%0,%1,%2,%3};"
        : "+f"(c[0]), "+f"(c[1]), "+f"(c[2]), "+f"(c[3])
        : "r"(a[0]), "r"(a[1]), "r"(a[2]), "r"(a[3]), "r"(b[0]), "r"(b[1]));
}

// pair-interleave within each group of 8 pairs: (q, q+4) become adjacent words
__device__ __forceinline__ int ilv(int p) {
    return (p & ~7) | (((p & 3) << 1) | ((p >> 2) & 1));
}

// ---------------- weight conversion to bf16 (bit-identical to old sts rounding) ----
__global__ void convw_kernel(const float* __restrict__ w_in, const float* __restrict__ w_out,
                             const float* __restrict__ w_fc, const float* __restrict__ w_proj)
{
    int i = blockIdx.x * 256 + threadIdx.x;
    int y = blockIdx.y;
    const float* s;
    __nv_bfloat16* d;
    int n;
    if (y == 0)      { s = w_in;   d = (__nv_bfloat16*)(g_scratch + O_WIN);   n = 3 * C_ * C_; }
    else if (y == 1) { s = w_out;  d = (__nv_bfloat16*)(g_scratch + O_WOUT);  n = C_ * C_; }
    else if (y == 2) { s = w_fc;   d = (__nv_bfloat16*)(g_scratch + O_WFC);   n = 4 * C_ * C_; }
    else             { s = w_proj; d = (__nv_bfloat16*)(g_scratch + O_WPROJ); n = 4 * C_ * C_; }
    if (i < n) d[i] = __float2bfloat16(s[i]);
}

// ---------------- LayerNorm (C=384, 128 threads), bf16 output ----
template<int AFFINE>
__global__ void ln_kernel(const float* __restrict__ in, __nv_bfloat16* __restrict__ out,
                          const float* __restrict__ gamma, const float* __restrict__ beta)
{
    long row = blockIdx.x;
    const float* x = in + row * C_;
    __nv_bfloat16* o = out + row * C_;
    int t = threadIdx.x;
    float v0 = x[t], v1 = x[t + 128], v2 = x[t + 256];
    float s = v0 + v1 + v2;
    float q = v0 * v0 + v1 * v1 + v2 * v2;
    __shared__ float sm[8];
    #pragma unroll
    for (int o2 = 16; o2; o2 >>= 1) {
        s += __shfl_xor_sync(0xffffffffu, s, o2);
        q += __shfl_xor_sync(0xffffffffu, q, o2);
    }
    int w = t >> 5;
    if ((t & 31) == 0) { sm[w] = s; sm[4 + w] = q; }
    __syncthreads();
    s = sm[0] + sm[1] + sm[2] + sm[3];
    q = sm[4] + sm[5] + sm[6] + sm[7];
    float mean = s * (1.f / C_);
    float var  = q * (1.f / C_) - mean * mean;
    float rstd = rsqrtf(var + 1e-5f);
    if (AFFINE) {
        o[t]       = __float2bfloat16((v0 - mean) * rstd * gamma[t]       + beta[t]);
        o[t + 128] = __float2bfloat16((v1 - mean) * rstd * gamma[t + 128] + beta[t + 128]);
        o[t + 256] = __float2bfloat16((v2 - mean) * rstd * gamma[t + 256] + beta[t + 256]);
    } else {
        o[t]       = __float2bfloat16((v0 - mean) * rstd);
        o[t + 128] = __float2bfloat16((v1 - mean) * rstd);
        o[t + 256] = __float2bfloat16((v2 - mean) * rstd);
    }
}

// ---- fused: feat(f32) = x2 minus cls rows ; xhat(bf16) = layernorm(feat) ----
__global__ void ln_feat_kernel()
{
    int n = blockIdx.x;
    long row = (long)n + (n >> 10) + 1;
    const float* x = g_scratch + O_X2 + row * C_;
    float* feat = g_scratch + O_FEAT + (long)n * C_;
    __nv_bfloat16* xhat = (__nv_bfloat16*)(g_scratch + O_LNB) + (long)n * C_;
    int t = threadIdx.x;
    float v0 = x[t], v1 = x[t + 128], v2 = x[t + 256];
    float s = v0 + v1 + v2;
    float q = v0 * v0 + v1 * v1 + v2 * v2;
    __shared__ float sm[8];
    #pragma unroll
    for (int o2 = 16; o2; o2 >>= 1) {
        s += __shfl_xor_sync(0xffffffffu, s, o2);
        q += __shfl_xor_sync(0xffffffffu, q, o2);
    }
    int w = t >> 5;
    if ((t & 31) == 0) { sm[w] = s; sm[4 + w] = q; }
    __syncthreads();
    s = sm[0] + sm[1] + sm[2] + sm[3];
    q = sm[4] + sm[5] + sm[6] + sm[7];
    float mean = s * (1.f / C_);
    float var  = q * (1.f / C_) - mean * mean;
    float rstd = rsqrtf(var + 1e-5f);
    feat[t]       = v0; xhat[t]       = __float2bfloat16((v0 - mean) * rstd);
    feat[t + 128] = v1; xhat[t + 128] = __float2bfloat16((v1 - mean) * rstd);
    feat[t + 256] = v2; xhat[t + 256] = __float2bfloat16((v2 - mean) * rstd);
}

// ---- fold LN3 affine into w_attn1 (bf16 out): W'[n][k]=W[n][k]*g[k], b'=b+W b3 ----
__global__ void foldw_kernel(const float* __restrict__ w, const float* __restrict__ bw,
                             const float* __restrict__ g, const float* __restrict__ b,
                             __nv_bfloat16* __restrict__ wout, float* __restrict__ bout)
{
    int n = blockIdx.x, z = blockIdx.y, t = threadIdx.x;
    const float* wr = w + ((long)z * C_ + n) * C_;
    const float* gz = g + (long)z * C_;
    const float* bz = b + (long)z * C_;
    __nv_bfloat16* wo = wout + ((long)z * C_ + n) * C_;
    float acc = 0.f;
    for (int c = t; c < C_; c += 128) {
        float wv = wr[c];
        wo[c] = __float2bfloat16(wv * gz[c]);
        acc += wv * bz[c];
    }
    #pragma unroll
    for (int o2 = 16; o2; o2 >>= 1) acc += __shfl_xor_sync(0xffffffffu, acc, o2);
    __shared__ float sr[4];
    if ((t & 31) == 0) sr[t >> 5] = acc;
    __syncthreads();
    if (t == 0) bout[(long)z * C_ + n] = sr[0] + sr[1] + sr[2] + sr[3] + bw[(long)z * C_ + n];
}

// ---------------- BF16 tensor-core NT GEMM: C[m,n] = sum_k A[m,k]*W[n,k] -----
// A and W both bf16 in gmem (uint pairs).
// MODE 1: +bias ; 2: quick_gelu(+bias) -> bf16 out ; 3: +bias + R1 ;
// MODE 4: (+bias)*mrow[m]+R1 ; 6: bf16 out, Q cols (n<C_) pre-scaled 0.125
template<int MODE>
__global__ void __launch_bounds__(128) gemm_bf16(
    const void* __restrict__ Av, const void* __restrict__ Wv,
    const float* __restrict__ bias, const float* __restrict__ R1,
    const float* __restrict__ mrow, float* __restrict__ Co,
    int Mr, int Nc, int K,
    long aZ, long wZ, long bZ, long cZ, long mZ, long r1Z)   // aZ/wZ in uints
{
    constexpr int BM = 128, BN = 64, BK = 16, LD = 12;   // LD in uint32 (bf16 pairs)
    __shared__ unsigned As[2][BM * LD];
    __shared__ unsigned Bs[2][BN * LD];
    int z = blockIdx.z;
    const unsigned* A = (const unsigned*)Av + (long)z * aZ;
    const unsigned* W = (const unsigned*)Wv + (long)z * wZ;
    const int KW = K / 2;                                 // uints per row
    bias += (long)z * bZ; Co += (long)z * cZ;
    if (MODE == 4) mrow += (long)z * mZ;
    if (MODE == 3 || MODE == 4) R1 += (long)z * r1Z;
    int m0 = blockIdx.y * BM, n0 = blockIdx.x * BN;
    int tid = threadIdx.x;

    int arow = tid >> 2;            // 0..31
    int c4 = tid & 3;               // float4-equivalent index within the 16-k stage
    int p0 = (c4 < 2) ? 4 * c4 : 4 * c4 - 7;    // interleaved pair position

    const unsigned* Ap[4]; bool am[4];
    #pragma unroll
    for (int i = 0; i < 4; i++) {
        int gm = m0 + arow + 32 * i;
        am[i] = gm < Mr;
        Ap[i] = A + (long)gm * KW + c4 * 2;
    }
    const unsigned* Wp0 = W + (long)(n0 + arow) * KW + c4 * 2;
    const unsigned* Wp1 = W + (long)(n0 + arow + 32) * KW + c4 * 2;

    uint2 ua[4], ub[2];
    auto ldg = [&](int k0) {
        int kw = k0 / 2;
        #pragma unroll
        for (int i = 0; i < 4; i++)
            ua[i] = am[i] ? *(const uint2*)(Ap[i] + kw) : make_uint2(0, 0);
        ub[0] = *(const uint2*)(Wp0 + kw);
        ub[1] = *(const uint2*)(Wp1 + kw);
    };
    auto sts = [&](int buf) {
        #pragma unroll
        for (int i = 0; i < 4; i++) {
            unsigned* p = &As[buf][(arow + 32 * i) * LD + p0];
            p[0] = ua[i].x;
            p[2] = ua[i].y;
        }
        #pragma unroll
        for (int j = 0; j < 2; j++) {
            unsigned* p = &Bs[buf][(arow + 32 * j) * LD + p0];
            p[0] = ub[j].x;
            p[2] = ub[j].y;
        }
    };

    int warp = tid >> 5, lane = tid & 31;
    int wm = (warp >> 1) * 64, wn = (warp & 1) * 32;
    int g = lane >> 2, r = lane & 3;

    float acc[4][4][4] = {};

    ldg(0);
    sts(0);
    __syncthreads();

    const int nstage = K / BK;
    int buf = 0;
    for (int s = 0; s < nstage; s++) {
        if (s + 1 < nstage) ldg((s + 1) * BK);
        unsigned af[4][4], bf[4][2];
        #pragma unroll
        for (int i = 0; i < 4; i++) {
            int mr_ = wm + 16 * i + g;
            uint2 va = *(const uint2*)&As[buf][mr_ * LD + 2 * r];
            uint2 vb = *(const uint2*)&As[buf][(mr_ + 8) * LD + 2 * r];
            af[i][0] = va.x; af[i][2] = va.y;
            af[i][1] = vb.x; af[i][3] = vb.y;
        }
        #pragma unroll
        for (int j = 0; j < 4; j++) {
            uint2 w2 = *(const uint2*)&Bs[buf][(wn + 8 * j + g) * LD + 2 * r];
            bf[j][0] = w2.x; bf[j][1] = w2.y;
        }
        #pragma unroll
        for (int i = 0; i < 4; i++)
            #pragma unroll
            for (int j = 0; j < 4; j++)
                mma_bf16(acc[i][j], af[i], bf[j]);
        if (s + 1 < nstage) sts(buf ^ 1);
        __syncthreads();
        buf ^= 1;
    }

    // epilogue
    __nv_bfloat16* CoH = (__nv_bfloat16*)Co;
    #pragma unroll
    for (int i = 0; i < 4; i++) {
        #pragma unroll
        for (int half = 0; half < 2; half++) {
            int m = m0 + wm + 16 * i + g + 8 * half;
            if (m >= Mr) continue;
            float msk = (MODE == 4) ? mrow[m] : 0.f;
            #pragma unroll
            for (int j = 0; j < 4; j++) {
                int n = n0 + wn + 8 * j + 2 * r;
                float v0 = acc[i][j][2 * half]     + bias[n];
                float v1 = acc[i][j][2 * half + 1] + bias[n + 1];
                long idx = (long)m * Nc + n;
                if (MODE == 6) {
                    float sc = (n < C_) ? 0.125f : 1.f;
                    *(unsigned*)(CoH + idx) = pack_bf16(v0 * sc, v1 * sc);
                    continue;
                }
                if (MODE == 2) {
                    *(unsigned*)(CoH + idx) = pack_bf16(
                        v0 / (1.f + __expf(-1.702f * v0)),
                        v1 / (1.f + __expf(-1.702f * v1)));
                    continue;
                }
                float r0, r1v;
                if (MODE == 1)      { r0 = v0; r1v = v1; }
                else if (MODE == 3) { r0 = v0 + R1[idx]; r1v = v1 + R1[idx + 1]; }
                else                { r0 = v0 * msk + R1[idx]; r1v = v1 * msk + R1[idx + 1]; }
                *(float2*)(Co + idx) = make_float2(r0, r1v);
            }
        }
    }
}

// ---------------- SIMT fallback GEMM (adapter shapes, f32) ----------------
// MODE 2: quick_gelu(+bias) ; 5: R1 + R2 + 0.5*(+bias)
template<int MODE>
__global__ void __launch_bounds__(256) gemm_nt(
    const float* __restrict__ A, const float* __restrict__ W,
    const float* __restrict__ bias, const float* __restrict__ R1,
    const float* __restrict__ R2, float* __restrict__ Co,
    int Mr, int Nc, int K)
{
    __shared__ float As[16][64];
    __shared__ float Ws[16][64];
    int m0 = blockIdx.y * 64, n0 = blockIdx.x * 64;
    int tid = threadIdx.x;
    int lr = tid >> 2, lk = (tid & 3) << 2;
    int ty = tid >> 4, tx = tid & 15;
    float acc[4][4] = {};
    for (int k0 = 0; k0 < K; k0 += 16) {
        float4 va = make_float4(0, 0, 0, 0), vw = make_float4(0, 0, 0, 0);
        int gm = m0 + lr;
        if (gm < Mr) va = *(const float4*)(A + (long)gm * K + (k0 + lk));
        int gn = n0 + lr;
        if (gn < Nc) vw = *(const float4*)(W + (long)gn * K + (k0 + lk));
        __syncthreads();
        As[lk][lr] = va.x; As[lk + 1][lr] = va.y; As[lk + 2][lr] = va.z; As[lk + 3][lr] = va.w;
        Ws[lk][lr] = vw.x; Ws[lk + 1][lr] = vw.y; Ws[lk + 2][lr] = vw.z; Ws[lk + 3][lr] = vw.w;
        __syncthreads();
        #pragma unroll
        for (int kk = 0; kk < 16; kk++) {
            float4 a4 = *(const float4*)&As[kk][ty << 2];
            float4 b4 = *(const float4*)&Ws[kk][tx << 2];
            acc[0][0] += a4.x * b4.x; acc[0][1] += a4.x * b4.y; acc[0][2] += a4.x * b4.z; acc[0][3] += a4.x * b4.w;
            acc[1][0] += a4.y * b4.x; acc[1][1] += a4.y * b4.y; acc[1][2] += a4.y * b4.z; acc[1][3] += a4.y * b4.w;
            acc[2][0] += a4.z * b4.x; acc[2][1] += a4.z * b4.y; acc[2][2] += a4.z * b4.z; acc[2][3] += a4.z * b4.w;
            acc[3][0] += a4.w * b4.x; acc[3][1] += a4.w * b4.y; acc[3][2] += a4.w * b4.z; acc[3][3] += a4.w * b4.w;
        }
    }
    #pragma unroll
    for (int i = 0; i < 4; i++) {
        int m = m0 + (ty << 2) + i;
        if (m >= Mr) continue;
        #pragma unroll
        for (int j = 0; j < 4; j++) {
            int n = n0 + (tx << 2) + j;
            if (n >= Nc) continue;
            float v = acc[i][j] + bias[n];
            long idx = (long)m * Nc + n;
            float rr;
            if (MODE == 2) rr = v / (1.f + __expf(-1.702f * v));
            else           rr = R1[idx] + R2[idx] + 0.5f * v;
            Co[idx] = rr;
        }
    }
}

// ---------------- bf16 tensor-core flash attention ----------------
// 128 q-rows per block (8 warps x m16), 64-key tiles, dh=64.
__global__ void __launch_bounds__(256, 2) attn_mma_kernel()
{
    constexpr int LDK = 36, LDVT = 36;   // words (bf16 pairs), 32 + pad
    __shared__ unsigned Ks[64 * LDK];
    __shared__ unsigned Vt[64 * LDVT];
    const unsigned* qkv = (const unsigned*)(g_scratch + O_QKV);
    const int RW = 3 * C_ / 2;
    __nv_bfloat16* attH = (__nv_bfloat16*)(g_scratch + O_ATT);
    int bh = blockIdx.y;
    int b = bh / H_, h = bh % H_;
    int q0 = blockIdx.x * 128;
    const unsigned* qb = qkv + (long)b * G_ * RW + h * (DH_ / 2);
    const unsigned* kb = qb + C_ / 2;
    const unsigned* vb = qb + C_;
    int tid = threadIdx.x, warp = tid >> 5, lane = tid & 31;
    int g = lane >> 2, r = lane & 3;

    unsigned qf[4][4];
    int qrow0 = q0 + warp * 16 + g;
    int qrow1 = qrow0 + 8;
    bool qv0 = qrow0 < G_, qv1 = qrow1 < G_;
    const unsigned* qp0 = qb + (long)qrow0 * RW;
    const unsigned* qp1 = qb + (long)qrow1 * RW;
    #pragma unroll
    for (int kbq = 0; kbq < 4; kbq++) {
        int u0 = kbq * 8 + r;
        qf[kbq][0] = qv0 ? qp0[u0]     : 0u;
        qf[kbq][1] = qv1 ? qp1[u0]     : 0u;
        qf[kbq][2] = qv0 ? qp0[u0 + 4] : 0u;
        qf[kbq][3] = qv1 ? qp1[u0 + 4] : 0u;
    }

    float o[8][4] = {};
    float m0v = -FLT_MAX, m1v = -FLT_MAX, l0 = 0.f, l1 = 0.f;
    unsigned short* VtS = (unsigned short*)Vt;

    for (int n0 = 0; n0 < G_; n0 += 64) {
        __syncthreads();
        #pragma unroll
        for (int it = 0; it < 4; it++) {
            int i = tid + it * 256;
            int key = i >> 4, c4 = i & 15;
            int gk = n0 + key;
            uint2 kv = make_uint2(0, 0), vv = make_uint2(0, 0);
            if (gk < G_) {
                kv = *(const uint2*)(kb + (long)gk * RW + c4 * 2);
                vv = *(const uint2*)(vb + (long)gk * RW + c4 * 2);
            }
            Ks[key * LDK + ilv(2 * c4)]     = kv.x;
            Ks[key * LDK + ilv(2 * c4 + 1)] = kv.y;
            int vword = ilv(key >> 1);
            int vhalf = key & 1;
            VtS[((4 * c4 + 0) * LDVT + vword) * 2 + vhalf] = (unsigned short)(vv.x & 0xffffu);
            VtS[((4 * c4 + 1) * LDVT + vword) * 2 + vhalf] = (unsigned short)(vv.x >> 16);
            VtS[((4 * c4 + 2) * LDVT + vword) * 2 + vhalf] = (unsigned short)(vv.y & 0xffffu);
            VtS[((4 * c4 + 3) * LDVT + vword) * 2 + vhalf] = (unsigned short)(vv.y >> 16);
        }
        __syncthreads();

        float s[8][4] = {};
        #pragma unroll
        for (int kbq = 0; kbq < 4; kbq++) {
            #pragma unroll
            for (int j = 0; j < 8; j++) {
                uint2 bv = *(const uint2*)&Ks[(j * 8 + g) * LDK + kbq * 8 + 2 * r];
                unsigned bfr[2] = {bv.x, bv.y};
                mma_bf16(s[j], qf[kbq], bfr);
            }
        }
        float mx0 = -FLT_MAX, mx1 = -FLT_MAX;
        #pragma unroll
        for (int j = 0; j < 8; j++) {
            int c = n0 + j * 8 + 2 * r;
            if (c >= G_)     { s[j][0] = -FLT_MAX; s[j][2] = -FLT_MAX; }
            if (c + 1 >= G_) { s[j][1] = -FLT_MAX; s[j][3] = -FLT_MAX; }
            mx0 = fmaxf(mx0, fmaxf(s[j][0], s[j][1]));
            mx1 = fmaxf(mx1, fmaxf(s[j][2], s[j][3]));
        }
        mx0 = fmaxf(mx0, __shfl_xor_sync(0xffffffffu, mx0, 1));
        mx0 = fmaxf(mx0, __shfl_xor_sync(0xffffffffu, mx0, 2));
        mx1 = fmaxf(mx1, __shfl_xor_sync(0xffffffffu, mx1, 1));
        mx1 = fmaxf(mx1, __shfl_xor_sync(0xffffffffu, mx1, 2));
        float mn0 = fmaxf(m0v, mx0), mn1 = fmaxf(m1v, mx1);
        float a0 = __expf(m0v - mn0), a1 = __expf(m1v - mn1);
        m0v = mn0; m1v = mn1;
        #pragma unroll
        for (int j = 0; j < 8; j++) {
            o[j][0] *= a0; o[j][1] *= a0; o[j][2] *= a1; o[j][3] *= a1;
        }

        float ps0 = 0.f, ps1 = 0.f;
        #pragma unroll
        for (int j = 0; j < 8; j++) {
            s[j][0] = __expf(s[j][0] - mn0);
            s[j][1] = __expf(s[j][1] - mn0);
            s[j][2] = __expf(s[j][2] - mn1);
            s[j][3] = __expf(s[j][3] - mn1);
            ps0 += s[j][0] + s[j][1];
            ps1 += s[j][2] + s[j][3];
        }
        ps0 += __shfl_xor_sync(0xffffffffu, ps0, 1);
        ps0 += __shfl_xor_sync(0xffffffffu, ps0, 2);
        ps1 += __shfl_xor_sync(0xffffffffu, ps1, 1);
        ps1 += __shfl_xor_sync(0xffffffffu, ps1, 2);
        l0 = l0 * a0 + ps0;
        l1 = l1 * a1 + ps1;

        #pragma unroll
        for (int kbq = 0; kbq < 4; kbq++) {
            unsigned af[4];
            af[0] = pack_bf16(s[2 * kbq][0],     s[2 * kbq][1]);
            af[1] = pack_bf16(s[2 * kbq][2],     s[2 * kbq][3]);
            af[2] = pack_bf16(s[2 * kbq + 1][0], s[2 * kbq + 1][1]);
            af[3] = pack_bf16(s[2 * kbq + 1][2], s[2 * kbq + 1][3]);
            #pragma unroll
            for (int j = 0; j < 8; j++) {
                uint2 vv = *(const uint2*)&Vt[(j * 8 + g) * LDVT + kbq * 8 + 2 * r];
                unsigned bfr[2] = {vv.x, vv.y};
                mma_bf16(o[j], af, bfr);
            }
        }
    }

    float inv0 = qv0 ? 1.f / l0 : 0.f;
    float inv1 = qv1 ? 1.f / l1 : 0.f;
    #pragma unroll
    for (int j = 0; j < 8; j++) {
        int c = h * DH_ + j * 8 + 2 * r;
        if (qv0) *(unsigned*)&attH[((long)b * G_ + qrow0) * C_ + c] =
            pack_bf16(o[j][0] * inv0, o[j][1] * inv0);
        if (qv1) *(unsigned*)&attH[((long)b * G_ + qrow1) * C_ + c] =
            pack_bf16(o[j][2] * inv1, o[j][3] * inv1);
    }
}

// ---------------- sorted-segment max+mean (M=1024 segments) ------------------
__global__ void seg3d_kernel(const int* __restrict__ sci, const int* __restrict__ segid)
{
    const float* feat = g_scratch + O_FEAT;
    float* t3 = g_scratch + O_T3D;
    int s = blockIdx.x;
    __shared__ int sh[2];
    if (threadIdx.x < 2) {
        int target = s + threadIdx.x;
        int lo = 0, hi = NPT_;
        while (lo < hi) { int mid = (lo + hi) >> 1; if (segid[mid] < target) lo = mid + 1; else hi = mid; }
        sh[threadIdx.x] = lo;
    }
    __syncthreads();
    int lo = sh[0], hi = sh[1];
    int t = threadIdx.x;
    float mx[3] = {-FLT_MAX, -FLT_MAX, -FLT_MAX};
    float sm[3] = {0, 0, 0};
    for (int r = lo; r < hi; r++) {
        int n = sci[r];
        const float* f = feat + (long)n * C_;
        #pragma unroll
        for (int j = 0; j < 3; j++) {
            float v = f[t + j * 128];
            mx[j] = fmaxf(mx[j], v);
            sm[j] += v;
        }
    }
    float cnt = (float)(hi - lo);
    float invc = 1.f / fmaxf(cnt, 1.f);
    #pragma unroll
    for (int j = 0; j < 3; j++) {
        float m_ = (hi > lo) ? mx[j] : 0.f;
        t3[(long)s * C_ + t + j * 128] = m_ + sm[j] * invc;
    }
}

// ---------------- CSR build for NS x 1536 segments ----------------
__global__ void zero_cnt_kernel()
{
    int i = blockIdx.x * 256 + threadIdx.x;
    if (i < NSEGT_) ((int*)(g_scratch + O_CNT))[i] = 0;
}

__global__ void cnt_kernel(const int* __restrict__ fgi)
{
    int i = blockIdx.x * 256 + threadIdx.x;
    if (i < NS_ * NPT_)
        atomicAdd((int*)(g_scratch + O_CNT) + (long)(i / NPT_) * SEG1_ + fgi[i], 1);
}

// per-branch exclusive scan: grid = NS_, 512 threads x 3 entries (SEG1_ = 1536)
__global__ void __launch_bounds__(512) scan_kernel()
{
    int z = blockIdx.x, t = threadIdx.x;
    const int* cnt = (const int*)(g_scratch + O_CNT) + (long)z * SEG1_;
    int* off = (int*)(g_scratch + O_OFF) + (long)z * SEG1_;
    int* cur = (int*)(g_scratch + O_CUR) + (long)z * SEG1_;
    int base = t * 3;
    int v0 = cnt[base], v1 = cnt[base + 1], v2 = cnt[base + 2];
    int tot = v0 + v1 + v2;
    int lane = t & 31, warp = t >> 5;    // 16 warps
    int inc = tot;
    #pragma unroll
    for (int o2 = 1; o2 < 32; o2 <<= 1) {
        int x = __shfl_up_sync(0xffffffffu, inc, o2);
        if (lane >= o2) inc += x;
    }
    __shared__ int ws[16];
    if (lane == 31) ws[warp] = inc;
    __syncthreads();
    if (warp == 0) {
        int wv = (lane < 16) ? ws[lane] : 0;
        int wi = wv;
        #pragma unroll
        for (int o2 = 1; o2 < 16; o2 <<= 1) {
            int x = __shfl_up_sync(0xffffffffu, wi, o2);
            if (lane >= o2) wi += x;
        }
        if (lane < 16) ws[lane] = wi - wv;
    }
    __syncthreads();
    int offv = z * NPT_ + ws[warp] + (inc - tot);
    off[base] = offv;     cur[base] = offv;     offv += v0;
    off[base + 1] = offv; cur[base + 1] = offv; offv += v1;
    off[base + 2] = offv; cur[base + 2] = offv;
}

__global__ void fill_kernel(const int* __restrict__ fgi)
{
    int i = blockIdx.x * 256 + threadIdx.x;
    if (i >= NS_ * NPT_) return;
    int s = i / NPT_, n = i - s * NPT_;
    int g = fgi[i];
    int pos = atomicAdd((int*)(g_scratch + O_CUR) + (long)s * SEG1_ + g, 1);
    ((int*)(g_scratch + O_LIST))[pos] = n;
}

// ---- gather-reduce: SUM1[z,seg,:] = max + mean over that segment's fx rows ----
__global__ void seg1d_kernel()
{
    int seg = blockIdx.x, z = blockIdx.y;
    long idx = (long)z * SEG1_ + seg;
    int lo = ((const int*)(g_scratch + O_OFF))[idx];
    int cnt = ((const int*)(g_scratch + O_CNT))[idx];
    const int* list = (const int*)(g_scratch + O_LIST);
    const float* fx = g_scratch + O_FX + (long)z * NPT_ * C_;
    int t = threadIdx.x;
    float mx[3] = {-FLT_MAX, -FLT_MAX, -FLT_MAX};
    float sm[3] = {0, 0, 0};
    for (int r = 0; r < cnt; r++) {
        const float* f = fx + (long)list[lo + r] * C_;
        #pragma unroll
        for (int j = 0; j < 3; j++) {
            float v = f[t + j * 128];
            mx[j] = fmaxf(mx[j], v);
            sm[j] += v;
        }
    }
    float invc = 1.f / fmaxf((float)cnt, 1.f);
    float* o = g_scratch + O_SUM1 + idx * C_;
    #pragma unroll
    for (int j = 0; j < 3; j++) {
        float m_ = (cnt > 0) ? mx[j] : 0.f;
        o[t + j * 128] = m_ + sm[j] * invc;
    }
}

// ---------------- batchnorm stats (per column over rows) ----------------
__global__ void bnstats_kernel(const float* __restrict__ in, float* __restrict__ mean,
                               float* __restrict__ rstd, int rows, long inZ)
{
    int c = blockIdx.x, z = blockIdx.y;
    in += (long)z * inZ;
    float s = 0.f, q = 0.f;
    for (int r = threadIdx.x; r < rows; r += blockDim.x) {
        float v = in[(long)r * C_ + c];
        s += v; q += v * v;
    }
    #pragma unroll
    for (int o2 = 16; o2; o2 >>= 1) {
        s += __shfl_xor_sync(0xffffffffu, s, o2);
        q += __shfl_xor_sync(0xffffffffu, q, o2);
    }
    __shared__ float ss[8], qq[8];
    int w = threadIdx.x >> 5;
    if ((threadIdx.x & 31) == 0) { ss[w] = s; qq[w] = q; }
    __syncthreads();
    if (threadIdx.x == 0) {
        float S = 0.f, Q = 0.f;
        #pragma unroll
        for (int i = 0; i < 8; i++) { S += ss[i]; Q += qq[i]; }
        float m = S / rows;
        float var = Q / rows - m * m;
        mean[(long)z * C_ + c] = m;
        rstd[(long)z * C_ + c] = rsqrtf(var + 1e-5f);
    }
}

// ---------------- batchnorm apply + exact GELU (3d branch only) ----------------
__global__ void bnapply_kernel(const float* __restrict__ in, float* __restrict__ out,
                               const float* __restrict__ mean, const float* __restrict__ rstd,
                               const float* __restrict__ gamma, const float* __restrict__ beta,
                               long total)
{
    long i = blockIdx.x * (long)blockDim.x + threadIdx.x;
    if (i >= total) return;
    long rz = i / C_;
    int c = (int)(i - rz * C_);
    float v = (in[i] - mean[c]) * rstd[c] * gamma[c] + beta[c];
    out[i] = v * normcdff(v);
}

// ---------------- final: gather, BN+gelu (1d fused), cosine weights, mix -----
__global__ void final_kernel(float* __restrict__ out,
                             const int* __restrict__ cluster, const int* __restrict__ fgi,
                             const float* __restrict__ g1d, const float* __restrict__ b1d)
{
    int n = blockIdx.x;
    int t = threadIdx.x;
    if (n >= NPT_) {                    // cls rows
        int b = n - NPT_;
        #pragma unroll
        for (int j = 0; j < 3; j++)
            out[(long)b * G_ * C_ + t + j * 128] = g_scratch[O_X2 + (long)b * G_ * C_ + t + j * 128];
        return;
    }
    __shared__ float sm[4];
    auto bsum = [&](float v) -> float {
        #pragma unroll
        for (int o2 = 16; o2; o2 >>= 1) v += __shfl_xor_sync(0xffffffffu, v, o2);
        int w = t >> 5;
        if ((t & 31) == 0) sm[w] = v;
        __syncthreads();
        float r = sm[0] + sm[1] + sm[2] + sm[3];
        __syncthreads();
        return r;
    };
    float r3[3];
    const float* p3 = g_scratch + O_BN3D + (long)cluster[n] * C_;
    float pn3 = 0.f;
    #pragma unroll
    for (int j = 0; j < 3; j++) { r3[j] = p3[t + j * 128]; pn3 += r3[j] * r3[j]; }
    float n3sq = bsum(pn3);
    float na = fmaxf(sqrtf(n3sq), 1e-8f);

    const float* mean1 = g_scratch + O_MEAN1;
    const float* rstd1 = g_scratch + O_RSTD1;

    float rs[6][3];
    float wts[6];
    float wsum = 0.f;
    for (int s = 0; s < NS_; s++) {
        const float* ps = g_scratch + O_SUM1 + ((long)s * SEG1_ + fgi[(long)s * NPT_ + n]) * C_;
        float pd = 0.f, pq = 0.f;
        #pragma unroll
        for (int j = 0; j < 3; j++) {
            int c = t + j * 128;
            long sc = (long)s * C_ + c;
            float bnv = (ps[c] - mean1[sc]) * rstd1[sc] * g1d[sc] + b1d[sc];
            float v = bnv * normcdff(bnv);
            rs[s][j] = v;
            pd += v * r3[j];
            pq += v * v;
        }
        float dot = bsum(pd);
        float nq = bsum(pq);
        float nb = fmaxf(sqrtf(nq), 1e-8f);
        float sim = dot / (na * nb);
        wts[s] = (sim + 1.f) * 0.5f;
        wsum += wts[s];
    }
    float invw = 1.f / wsum;
    long orow = (long)n + (n >> 10) + 1;
    #pragma unroll
    for (int j = 0; j < 3; j++) {
        int c = t + j * 128;
        float acc = 0.f;
        #pragma unroll
        for (int s = 0; s < NS_; s++) acc += rs[s][j] * wts[s];
        out[orow * C_ + c] = g_scratch[O_FEAT + (long)n * C_ + c] + 0.3f * acc * invw;
    }
}

// ---------------- host launch ----------------
extern "C" void kernel_launch(void* const* d_in, const int* in_sizes, int n_in,
                              void* d_out, int out_size)
{
    const float* x      = (const float*)d_in[0];
    const float* mask   = (const float*)d_in[1];
    const float* ln1_g  = (const float*)d_in[2];
    const float* ln1_b  = (const float*)d_in[3];
    const float* ln2_g  = (const float*)d_in[4];
    const float* ln2_b  = (const float*)d_in[5];
    const float* w_in   = (const float*)d_in[6];
    const float* b_in   = (const float*)d_in[7];
    const float* w_out  = (const float*)d_in[8];
    const float* b_out  = (const float*)d_in[9];
    const float* w_fc   = (const float*)d_in[10];
    const float* b_fc   = (const float*)d_in[11];
    const float* w_proj = (const float*)d_in[12];
    const float* b_proj = (const float*)d_in[13];
    const float* wa1    = (const float*)d_in[14];
    const float* ba1    = (const float*)d_in[15];
    const float* wa2    = (const float*)d_in[16];
    const float* ba2    = (const float*)d_in[17];
    const float* g3     = (const float*)d_in[18];
    const float* b3     = (const float*)d_in[19];
    const float* g1d    = (const float*)d_in[20];
    const float* b1d    = (const float*)d_in[21];
    const float* gn3    = (const float*)d_in[22];
    const float* bn3    = (const float*)d_in[23];
    const float* w_attn1= (const float*)d_in[24];
    const float* b_attn1= (const float*)d_in[25];
    const int* sci      = (const int*)d_in[26];
    const int* segid    = (const int*)d_in[27];
    const int* cluster  = (const int*)d_in[28];
    const int* fgi      = (const int*)d_in[29];
    float* out = (float*)d_out;

    float* base = nullptr;
    cudaGetSymbolAddress((void**)&base, g_scratch);

    const int MTB  = (ROWS_ + 127) / 128;   // 65
    const int MTBp = NPT_ / 128;            // 64
    const int MT64 = (ROWS_ + 63) / 64;     // 129

    // 0) independent prep: weight conversions + fold + CSR build
    convw_kernel<<<dim3((4 * C_ * C_ + 255) / 256, 4), 256>>>(w_in, w_out, w_fc, w_proj);
    foldw_kernel<<<dim3(C_, NS_), 128>>>(w_attn1, b_attn1, gn3, bn3,
                                         (__nv_bfloat16*)(base + O_WATT), base + O_BATT);
    zero_cnt_kernel<<<(NSEGT_ + 255) / 256, 256>>>();
    cnt_kernel<<<(NS_ * NPT_ + 255) / 256, 256>>>(fgi);
    scan_kernel<<<NS_, 512>>>();
    fill_kernel<<<(NS_ * NPT_ + 255) / 256, 256>>>(fgi);
    // 1) LN1 -> bf16
    ln_kernel<1><<<ROWS_, 128>>>(x, (__nv_bfloat16*)(base + O_LN), ln1_g, ln1_b);
    // 2) QKV = LN1 @ w_in^T + b_in -> bf16 (Q pre-scaled by 0.125)
    gemm_bf16<6><<<dim3((3 * C_) / 64, MTB, 1), 128>>>(
        base + O_LN, base + O_WIN, b_in, nullptr, nullptr,
        base + O_QKV, ROWS_, 3 * C_, C_, 0, 0, 0, 0, 0, 0);
    // 3) attention (bf16 in/out, 128 q rows/block)
    attn_mma_kernel<<<dim3((G_ + 127) / 128, B_ * H_), 256>>>();
    // 4) out proj + residual x  -> x1 (f32)
    gemm_bf16<3><<<dim3(C_ / 64, MTB, 1), 128>>>(
        base + O_ATT, base + O_WOUT, b_out, x, nullptr,
        base + O_X1, ROWS_, C_, C_, 0, 0, 0, 0, 0, 0);
    // 5) LN2 -> bf16
    ln_kernel<1><<<ROWS_, 128>>>(base + O_X1, (__nv_bfloat16*)(base + O_LN), ln2_g, ln2_b);
    // 6) fc + quick_gelu -> HFC bf16
    gemm_bf16<2><<<dim3(4 * C_ / 64, MTB, 1), 128>>>(
        base + O_LN, base + O_WFC, b_fc, nullptr, nullptr,
        base + O_HFC, ROWS_, 4 * C_, C_, 0, 0, 0, 0, 0, 0);
    // 7) proj (K=1536) -> XFFN f32
    gemm_bf16<1><<<dim3(C_ / 64, MTB, 1), 128>>>(
        base + O_HFC, base + O_WPROJ, b_proj, nullptr, nullptr,
        base + O_XFFN, ROWS_, C_, 4 * C_, 0, 0, 0, 0, 0, 0);
    // 8) adapter in + quick_gelu (SIMT fp32: N=48)
    gemm_nt<2><<<dim3(1, MT64, 1), 256>>>(
        base + O_XFFN, wa1, ba1, nullptr, nullptr,
        base + O_A1, ROWS_, 48, C_);
    // 9) adapter out + combine: x2 = x1 + xffn + 0.5*(a1@wa2^T + ba2) (SIMT: K=48)
    gemm_nt<5><<<dim3(C_ / 64, MT64, 1), 256>>>(
        base + O_A1, wa2, ba2, base + O_X1, base + O_XFFN,
        base + O_X2, ROWS_, C_, 48);
    // 10+11) feat(f32) = x2 minus cls rows, xhat(bf16) = layernorm(feat)
    ln_feat_kernel<<<NPT_, 128>>>();
    // 12) fx = (xhat @ W'^T + b')*mask + feat, batched over NS
    gemm_bf16<4><<<dim3(C_ / 64, MTBp, NS_), 128>>>(
        base + O_LNB, base + O_WATT, base + O_BATT, base + O_FEAT, mask,
        base + O_FX, NPT_, C_, C_,
        0, (long)C_ * C_ / 2, C_, (long)NPT_ * C_, NPT_, 0);
    // 13) sorted segment max+mean -> t3d (3d branch)
    seg3d_kernel<<<MSEG_, 128>>>(sci, segid);
    // 14) BN stats + apply(gelu) for 3d branch
    bnstats_kernel<<<dim3(C_, 1), 256>>>(base + O_T3D, base + O_MEAN3, base + O_RSTD3, MSEG_, 0);
    bnapply_kernel<<<(int)(((long)MSEG_ * C_ + 255) / 256), 256>>>(
        base + O_T3D, base + O_BN3D, base + O_MEAN3, base + O_RSTD3,
        g3, b3, (long)MSEG_ * C_);
    // 15) CSR gather-reduce: per-(branch,segment) max+mean -> SUM1
    seg1d_kernel<<<dim3(SEG1_, NS_), 128>>>();
    // 16) BN stats for 1d branches (apply fused into final)
    bnstats_kernel<<<dim3(C_, NS_), 256>>>(base + O_SUM1, base + O_MEAN1, base + O_RSTD1,
                                           SEG1_, (long)SEG1_ * C_);
    // 17) final: gather + fused 1d BN/gelu + cosine mix + output
    final_kernel<<<ROWS_, 128>>>(out, cluster, fgi, g1d, b1d);
}

// round 14
// speedup vs baseline: 1.0114x; 1.0114x over previous
#include <cuda_runtime.h>
#include <cuda_bf16.h>
#include <float.h>
#include <math.h>

// ---------------- problem constants ----------------
namespace cfg {
constexpr int B_ = 8, G_ = 1025, GP_ = 1024, C_ = 384, H_ = 6, DH_ = 64;
constexpr int NS_ = 6, MSEG_ = 1024, SEG1_ = 1536;      // SEG1 = B*GRID
constexpr int NPT_ = B_ * GP_;                          // 8192 points
constexpr int ROWS_ = B_ * G_;                          // 8200 rows incl cls
constexpr int NSEGT_ = NS_ * SEG1_;                     // 9216

// scratch layout (floats; several regions hold bf16 and use half)
constexpr long O_LN   = 0;                              // bf16
constexpr long O_QKV  = O_LN   + (long)ROWS_ * C_;      // bf16
constexpr long O_ATT  = O_QKV  + (long)ROWS_ * 3 * C_;  // bf16
constexpr long O_X1   = O_ATT  + (long)ROWS_ * C_;
constexpr long O_HFC  = O_X1   + (long)ROWS_ * C_;      // bf16
constexpr long O_XFFN = O_HFC  + (long)ROWS_ * 4 * C_;
constexpr long O_A1   = O_XFFN + (long)ROWS_ * C_;
constexpr long O_X2   = O_A1   + (long)ROWS_ * 48;
constexpr long O_FEAT = O_X2   + (long)ROWS_ * C_;
constexpr long O_LNB  = O_FEAT + (long)NPT_ * C_;       // bf16
constexpr long O_FX   = O_LNB  + (long)NPT_ * C_;
constexpr long O_T3D  = O_FX   + (long)NS_ * NPT_ * C_;
constexpr long O_BN3D = O_T3D  + (long)MSEG_ * C_;
constexpr long O_MEAN3= O_BN3D + (long)MSEG_ * C_;
constexpr long O_RSTD3= O_MEAN3+ C_;
constexpr long O_SUM1 = O_RSTD3+ C_;
constexpr long O_BN1D = O_SUM1 + (long)NSEGT_ * C_;
constexpr long O_MEAN1= O_BN1D + (long)NSEGT_ * C_;
constexpr long O_RSTD1= O_MEAN1+ (long)NS_ * C_;
constexpr long O_WATT = O_RSTD1+ (long)NS_ * C_;        // bf16
constexpr long O_BATT = O_WATT + (long)NS_ * C_ * C_ / 2;
constexpr long O_WIN  = O_BATT + (long)NS_ * C_;        // bf16
constexpr long O_WOUT = O_WIN  + (long)3 * C_ * C_ / 2; // bf16
constexpr long O_WFC  = O_WOUT + (long)C_ * C_ / 2;     // bf16
constexpr long O_WPROJ= O_WFC  + (long)4 * C_ * C_ / 2; // bf16
constexpr long O_CNT  = O_WPROJ+ (long)4 * C_ * C_ / 2; // int[NSEGT]
constexpr long O_OFF  = O_CNT  + NSEGT_;                // int[NSEGT]
constexpr long O_CUR  = O_OFF  + NSEGT_;                // int[NSEGT]
constexpr long O_LIST = O_CUR  + NSEGT_;                // int[NS*NPT]
constexpr long TOTAL  = O_LIST + (long)NS_ * NPT_;
}
using namespace cfg;

__device__ __align__(16) float g_scratch[TOTAL];

// ---------------- helpers ----------------
__device__ __forceinline__ unsigned pack_bf16(float lo, float hi) {
    unsigned r;
    asm("cvt.rn.bf16x2.f32 %0, %1, %2;" : "=r"(r) : "f"(hi), "f"(lo));
    return r;
}

__device__ __forceinline__ void mma_bf16(float c[4], const unsigned a[4], const unsigned b[2]) {
    asm volatile(
        "mma.sync.aligned.m16n8k16.row.col.f32.bf16.bf16.f32 "
        "{%0,%1,%2,%3},{%4,%5,%6,%7},{%8,%9},{%0,%1,%2,%3};"
        : "+f"(c[0]), "+f"(c[1]), "+f"(c[2]), "+f"(c[3])
        : "r"(a[0]), "r"(a[1]), "r"(a[2]), "r"(a[3]), "r"(b[0]), "r"(b[1]));
}

// pair-interleave within each group of 8 pairs: (q, q+4) become adjacent words
__device__ __forceinline__ int ilv(int p) {
    return (p & ~7) | (((p & 3) << 1) | ((p >> 2) & 1));
}

// ---------------- weight conversion to bf16 (bit-identical to sts rounding) ----
__global__ void convw_kernel(const float* __restrict__ w_in, const float* __restrict__ w_out,
                             const float* __restrict__ w_fc, const float* __restrict__ w_proj)
{
    int i = blockIdx.x * 256 + threadIdx.x;
    int y = blockIdx.y;
    const float* s;
    __nv_bfloat16* d;
    int n;
    if (y == 0)      { s = w_in;   d = (__nv_bfloat16*)(g_scratch + O_WIN);   n = 3 * C_ * C_; }
    else if (y == 1) { s = w_out;  d = (__nv_bfloat16*)(g_scratch + O_WOUT);  n = C_ * C_; }
    else if (y == 2) { s = w_fc;   d = (__nv_bfloat16*)(g_scratch + O_WFC);   n = 4 * C_ * C_; }
    else             { s = w_proj; d = (__nv_bfloat16*)(g_scratch + O_WPROJ); n = 4 * C_ * C_; }
    if (i < n) d[i] = __float2bfloat16(s[i]);
}

// ---------------- LayerNorm (C=384, 128 threads), bf16 output ----
template<int AFFINE>
__global__ void ln_kernel(const float* __restrict__ in, __nv_bfloat16* __restrict__ out,
                          const float* __restrict__ gamma, const float* __restrict__ beta)
{
    long row = blockIdx.x;
    const float* x = in + row * C_;
    __nv_bfloat16* o = out + row * C_;
    int t = threadIdx.x;
    float v0 = x[t], v1 = x[t + 128], v2 = x[t + 256];
    float s = v0 + v1 + v2;
    float q = v0 * v0 + v1 * v1 + v2 * v2;
    __shared__ float sm[8];
    #pragma unroll
    for (int o2 = 16; o2; o2 >>= 1) {
        s += __shfl_xor_sync(0xffffffffu, s, o2);
        q += __shfl_xor_sync(0xffffffffu, q, o2);
    }
    int w = t >> 5;
    if ((t & 31) == 0) { sm[w] = s; sm[4 + w] = q; }
    __syncthreads();
    s = sm[0] + sm[1] + sm[2] + sm[3];
    q = sm[4] + sm[5] + sm[6] + sm[7];
    float mean = s * (1.f / C_);
    float var  = q * (1.f / C_) - mean * mean;
    float rstd = rsqrtf(var + 1e-5f);
    if (AFFINE) {
        o[t]       = __float2bfloat16((v0 - mean) * rstd * gamma[t]       + beta[t]);
        o[t + 128] = __float2bfloat16((v1 - mean) * rstd * gamma[t + 128] + beta[t + 128]);
        o[t + 256] = __float2bfloat16((v2 - mean) * rstd * gamma[t + 256] + beta[t + 256]);
    } else {
        o[t]       = __float2bfloat16((v0 - mean) * rstd);
        o[t + 128] = __float2bfloat16((v1 - mean) * rstd);
        o[t + 256] = __float2bfloat16((v2 - mean) * rstd);
    }
}

// ---- fused: feat(f32) = x2 minus cls rows ; xhat(bf16) = layernorm(feat) ----
__global__ void ln_feat_kernel()
{
    int n = blockIdx.x;
    long row = (long)n + (n >> 10) + 1;
    const float* x = g_scratch + O_X2 + row * C_;
    float* feat = g_scratch + O_FEAT + (long)n * C_;
    __nv_bfloat16* xhat = (__nv_bfloat16*)(g_scratch + O_LNB) + (long)n * C_;
    int t = threadIdx.x;
    float v0 = x[t], v1 = x[t + 128], v2 = x[t + 256];
    float s = v0 + v1 + v2;
    float q = v0 * v0 + v1 * v1 + v2 * v2;
    __shared__ float sm[8];
    #pragma unroll
    for (int o2 = 16; o2; o2 >>= 1) {
        s += __shfl_xor_sync(0xffffffffu, s, o2);
        q += __shfl_xor_sync(0xffffffffu, q, o2);
    }
    int w = t >> 5;
    if ((t & 31) == 0) { sm[w] = s; sm[4 + w] = q; }
    __syncthreads();
    s = sm[0] + sm[1] + sm[2] + sm[3];
    q = sm[4] + sm[5] + sm[6] + sm[7];
    float mean = s * (1.f / C_);
    float var  = q * (1.f / C_) - mean * mean;
    float rstd = rsqrtf(var + 1e-5f);
    feat[t]       = v0; xhat[t]       = __float2bfloat16((v0 - mean) * rstd);
    feat[t + 128] = v1; xhat[t + 128] = __float2bfloat16((v1 - mean) * rstd);
    feat[t + 256] = v2; xhat[t + 256] = __float2bfloat16((v2 - mean) * rstd);
}

// ---- fold LN3 affine into w_attn1 (bf16 out): W'[n][k]=W[n][k]*g[k], b'=b+W b3 ----
__global__ void foldw_kernel(const float* __restrict__ w, const float* __restrict__ bw,
                             const float* __restrict__ g, const float* __restrict__ b,
                             __nv_bfloat16* __restrict__ wout, float* __restrict__ bout)
{
    int n = blockIdx.x, z = blockIdx.y, t = threadIdx.x;
    const float* wr = w + ((long)z * C_ + n) * C_;
    const float* gz = g + (long)z * C_;
    const float* bz = b + (long)z * C_;
    __nv_bfloat16* wo = wout + ((long)z * C_ + n) * C_;
    float acc = 0.f;
    for (int c = t; c < C_; c += 128) {
        float wv = wr[c];
        wo[c] = __float2bfloat16(wv * gz[c]);
        acc += wv * bz[c];
    }
    #pragma unroll
    for (int o2 = 16; o2; o2 >>= 1) acc += __shfl_xor_sync(0xffffffffu, acc, o2);
    __shared__ float sr[4];
    if ((t & 31) == 0) sr[t >> 5] = acc;
    __syncthreads();
    if (t == 0) bout[(long)z * C_ + n] = sr[0] + sr[1] + sr[2] + sr[3] + bw[(long)z * C_ + n];
}

// ---------------- BF16 tensor-core NT GEMM: C[m,n] = sum_k A[m,k]*W[n,k] -----
// A and W both bf16 in gmem (uint pairs).
// MODE 1: +bias ; 2: quick_gelu(+bias) -> bf16 out ; 3: +bias + R1 ;
// MODE 4: (+bias)*mrow[m]+R1 ; 6: bf16 out, Q cols (n<C_) pre-scaled 0.125
template<int MODE>
__global__ void __launch_bounds__(128) gemm_bf16(
    const void* __restrict__ Av, const void* __restrict__ Wv,
    const float* __restrict__ bias, const float* __restrict__ R1,
    const float* __restrict__ mrow, float* __restrict__ Co,
    int Mr, int Nc, int K,
    long aZ, long wZ, long bZ, long cZ, long mZ, long r1Z)   // aZ/wZ in uints
{
    constexpr int BM = 128, BN = 64, BK = 16, LD = 12;   // LD in uint32 (bf16 pairs)
    __shared__ unsigned As[2][BM * LD];
    __shared__ unsigned Bs[2][BN * LD];
    int z = blockIdx.z;
    const unsigned* A = (const unsigned*)Av + (long)z * aZ;
    const unsigned* W = (const unsigned*)Wv + (long)z * wZ;
    const int KW = K / 2;                                 // uints per row
    bias += (long)z * bZ; Co += (long)z * cZ;
    if (MODE == 4) mrow += (long)z * mZ;
    if (MODE == 3 || MODE == 4) R1 += (long)z * r1Z;
    int m0 = blockIdx.y * BM, n0 = blockIdx.x * BN;
    int tid = threadIdx.x;

    int arow = tid >> 2;            // 0..31
    int c4 = tid & 3;
    int p0 = (c4 < 2) ? 4 * c4 : 4 * c4 - 7;    // interleaved pair position

    const unsigned* Ap[4]; bool am[4];
    #pragma unroll
    for (int i = 0; i < 4; i++) {
        int gm = m0 + arow + 32 * i;
        am[i] = gm < Mr;
        Ap[i] = A + (long)gm * KW + c4 * 2;
    }
    const unsigned* Wp0 = W + (long)(n0 + arow) * KW + c4 * 2;
    const unsigned* Wp1 = W + (long)(n0 + arow + 32) * KW + c4 * 2;

    uint2 ua[4], ub[2];
    auto ldg = [&](int k0) {
        int kw = k0 / 2;
        #pragma unroll
        for (int i = 0; i < 4; i++)
            ua[i] = am[i] ? *(const uint2*)(Ap[i] + kw) : make_uint2(0, 0);
        ub[0] = *(const uint2*)(Wp0 + kw);
        ub[1] = *(const uint2*)(Wp1 + kw);
    };
    auto sts = [&](int buf) {
        #pragma unroll
        for (int i = 0; i < 4; i++) {
            unsigned* p = &As[buf][(arow + 32 * i) * LD + p0];
            p[0] = ua[i].x;
            p[2] = ua[i].y;
        }
        #pragma unroll
        for (int j = 0; j < 2; j++) {
            unsigned* p = &Bs[buf][(arow + 32 * j) * LD + p0];
            p[0] = ub[j].x;
            p[2] = ub[j].y;
        }
    };

    int warp = tid >> 5, lane = tid & 31;
    int wm = (warp >> 1) * 64, wn = (warp & 1) * 32;
    int g = lane >> 2, r = lane & 3;

    float acc[4][4][4] = {};

    ldg(0);
    sts(0);
    __syncthreads();

    const int nstage = K / BK;
    int buf = 0;
    for (int s = 0; s < nstage; s++) {
        if (s + 1 < nstage) ldg((s + 1) * BK);
        unsigned af[4][4], bf[4][2];
        #pragma unroll
        for (int i = 0; i < 4; i++) {
            int mr_ = wm + 16 * i + g;
            uint2 va = *(const uint2*)&As[buf][mr_ * LD + 2 * r];
            uint2 vb = *(const uint2*)&As[buf][(mr_ + 8) * LD + 2 * r];
            af[i][0] = va.x; af[i][2] = va.y;
            af[i][1] = vb.x; af[i][3] = vb.y;
        }
        #pragma unroll
        for (int j = 0; j < 4; j++) {
            uint2 w2 = *(const uint2*)&Bs[buf][(wn + 8 * j + g) * LD + 2 * r];
            bf[j][0] = w2.x; bf[j][1] = w2.y;
        }
        #pragma unroll
        for (int i = 0; i < 4; i++)
            #pragma unroll
            for (int j = 0; j < 4; j++)
                mma_bf16(acc[i][j], af[i], bf[j]);
        if (s + 1 < nstage) sts(buf ^ 1);
        __syncthreads();
        buf ^= 1;
    }

    // epilogue
    __nv_bfloat16* CoH = (__nv_bfloat16*)Co;
    #pragma unroll
    for (int i = 0; i < 4; i++) {
        #pragma unroll
        for (int half = 0; half < 2; half++) {
            int m = m0 + wm + 16 * i + g + 8 * half;
            if (m >= Mr) continue;
            float msk = (MODE == 4) ? mrow[m] : 0.f;
            #pragma unroll
            for (int j = 0; j < 4; j++) {
                int n = n0 + wn + 8 * j + 2 * r;
                float v0 = acc[i][j][2 * half]     + bias[n];
                float v1 = acc[i][j][2 * half + 1] + bias[n + 1];
                long idx = (long)m * Nc + n;
                if (MODE == 6) {
                    float sc = (n < C_) ? 0.125f : 1.f;
                    *(unsigned*)(CoH + idx) = pack_bf16(v0 * sc, v1 * sc);
                    continue;
                }
                if (MODE == 2) {
                    *(unsigned*)(CoH + idx) = pack_bf16(
                        v0 / (1.f + __expf(-1.702f * v0)),
                        v1 / (1.f + __expf(-1.702f * v1)));
                    continue;
                }
                float r0, r1v;
                if (MODE == 1)      { r0 = v0; r1v = v1; }
                else if (MODE == 3) { r0 = v0 + R1[idx]; r1v = v1 + R1[idx + 1]; }
                else                { r0 = v0 * msk + R1[idx]; r1v = v1 * msk + R1[idx + 1]; }
                *(float2*)(Co + idx) = make_float2(r0, r1v);
            }
        }
    }
}

// ---------------- SIMT fallback GEMM (adapter shapes, f32) ----------------
// MODE 2: quick_gelu(+bias) ; 5: R1 + R2 + 0.5*(+bias)
template<int MODE>
__global__ void __launch_bounds__(256) gemm_nt(
    const float* __restrict__ A, const float* __restrict__ W,
    const float* __restrict__ bias, const float* __restrict__ R1,
    const float* __restrict__ R2, float* __restrict__ Co,
    int Mr, int Nc, int K)
{
    __shared__ float As[16][64];
    __shared__ float Ws[16][64];
    int m0 = blockIdx.y * 64, n0 = blockIdx.x * 64;
    int tid = threadIdx.x;
    int lr = tid >> 2, lk = (tid & 3) << 2;
    int ty = tid >> 4, tx = tid & 15;
    float acc[4][4] = {};
    for (int k0 = 0; k0 < K; k0 += 16) {
        float4 va = make_float4(0, 0, 0, 0), vw = make_float4(0, 0, 0, 0);
        int gm = m0 + lr;
        if (gm < Mr) va = *(const float4*)(A + (long)gm * K + (k0 + lk));
        int gn = n0 + lr;
        if (gn < Nc) vw = *(const float4*)(W + (long)gn * K + (k0 + lk));
        __syncthreads();
        As[lk][lr] = va.x; As[lk + 1][lr] = va.y; As[lk + 2][lr] = va.z; As[lk + 3][lr] = va.w;
        Ws[lk][lr] = vw.x; Ws[lk + 1][lr] = vw.y; Ws[lk + 2][lr] = vw.z; Ws[lk + 3][lr] = vw.w;
        __syncthreads();
        #pragma unroll
        for (int kk = 0; kk < 16; kk++) {
            float4 a4 = *(const float4*)&As[kk][ty << 2];
            float4 b4 = *(const float4*)&Ws[kk][tx << 2];
            acc[0][0] += a4.x * b4.x; acc[0][1] += a4.x * b4.y; acc[0][2] += a4.x * b4.z; acc[0][3] += a4.x * b4.w;
            acc[1][0] += a4.y * b4.x; acc[1][1] += a4.y * b4.y; acc[1][2] += a4.y * b4.z; acc[1][3] += a4.y * b4.w;
            acc[2][0] += a4.z * b4.x; acc[2][1] += a4.z * b4.y; acc[2][2] += a4.z * b4.z; acc[2][3] += a4.z * b4.w;
            acc[3][0] += a4.w * b4.x; acc[3][1] += a4.w * b4.y; acc[3][2] += a4.w * b4.z; acc[3][3] += a4.w * b4.w;
        }
    }
    #pragma unroll
    for (int i = 0; i < 4; i++) {
        int m = m0 + (ty << 2) + i;
        if (m >= Mr) continue;
        #pragma unroll
        for (int j = 0; j < 4; j++) {
            int n = n0 + (tx << 2) + j;
            if (n >= Nc) continue;
            float v = acc[i][j] + bias[n];
            long idx = (long)m * Nc + n;
            float rr;
            if (MODE == 2) rr = v / (1.f + __expf(-1.702f * v));
            else           rr = R1[idx] + R2[idx] + 0.5f * v;
            Co[idx] = rr;
        }
    }
}

// ---------------- bf16 tensor-core flash attention ----------------
// 128 q-rows per block (8 warps x m16), 64-key tiles, dh=64.
__global__ void __launch_bounds__(256, 2) attn_mma_kernel()
{
    constexpr int LDK = 36, LDVT = 36;   // words (bf16 pairs), 32 + pad
    __shared__ unsigned Ks[64 * LDK];
    __shared__ unsigned Vt[64 * LDVT];
    const unsigned* qkv = (const unsigned*)(g_scratch + O_QKV);
    const int RW = 3 * C_ / 2;
    __nv_bfloat16* attH = (__nv_bfloat16*)(g_scratch + O_ATT);
    int bh = blockIdx.y;
    int b = bh / H_, h = bh % H_;
    int q0 = blockIdx.x * 128;
    const unsigned* qb = qkv + (long)b * G_ * RW + h * (DH_ / 2);
    const unsigned* kb = qb + C_ / 2;
    const unsigned* vb = qb + C_;
    int tid = threadIdx.x, warp = tid >> 5, lane = tid & 31;
    int g = lane >> 2, r = lane & 3;

    unsigned qf[4][4];
    int qrow0 = q0 + warp * 16 + g;
    int qrow1 = qrow0 + 8;
    bool qv0 = qrow0 < G_, qv1 = qrow1 < G_;
    const unsigned* qp0 = qb + (long)qrow0 * RW;
    const unsigned* qp1 = qb + (long)qrow1 * RW;
    #pragma unroll
    for (int kbq = 0; kbq < 4; kbq++) {
        int u0 = kbq * 8 + r;
        qf[kbq][0] = qv0 ? qp0[u0]     : 0u;
        qf[kbq][1] = qv1 ? qp1[u0]     : 0u;
        qf[kbq][2] = qv0 ? qp0[u0 + 4] : 0u;
        qf[kbq][3] = qv1 ? qp1[u0 + 4] : 0u;
    }

    float o[8][4] = {};
    float m0v = -FLT_MAX, m1v = -FLT_MAX, l0 = 0.f, l1 = 0.f;
    unsigned short* VtS = (unsigned short*)Vt;

    for (int n0 = 0; n0 < G_; n0 += 64) {
        __syncthreads();
        #pragma unroll
        for (int it = 0; it < 4; it++) {
            int i = tid + it * 256;
            int key = i >> 4, c4 = i & 15;
            int gk = n0 + key;
            uint2 kv = make_uint2(0, 0), vv = make_uint2(0, 0);
            if (gk < G_) {
                kv = *(const uint2*)(kb + (long)gk * RW + c4 * 2);
                vv = *(const uint2*)(vb + (long)gk * RW + c4 * 2);
            }
            Ks[key * LDK + ilv(2 * c4)]     = kv.x;
            Ks[key * LDK + ilv(2 * c4 + 1)] = kv.y;
            int vword = ilv(key >> 1);
            int vhalf = key & 1;
            VtS[((4 * c4 + 0) * LDVT + vword) * 2 + vhalf] = (unsigned short)(vv.x & 0xffffu);
            VtS[((4 * c4 + 1) * LDVT + vword) * 2 + vhalf] = (unsigned short)(vv.x >> 16);
            VtS[((4 * c4 + 2) * LDVT + vword) * 2 + vhalf] = (unsigned short)(vv.y & 0xffffu);
            VtS[((4 * c4 + 3) * LDVT + vword) * 2 + vhalf] = (unsigned short)(vv.y >> 16);
        }
        __syncthreads();

        float s[8][4] = {};
        #pragma unroll
        for (int kbq = 0; kbq < 4; kbq++) {
            #pragma unroll
            for (int j = 0; j < 8; j++) {
                uint2 bv = *(const uint2*)&Ks[(j * 8 + g) * LDK + kbq * 8 + 2 * r];
                unsigned bfr[2] = {bv.x, bv.y};
                mma_bf16(s[j], qf[kbq], bfr);
            }
        }
        float mx0 = -FLT_MAX, mx1 = -FLT_MAX;
        #pragma unroll
        for (int j = 0; j < 8; j++) {
            int c = n0 + j * 8 + 2 * r;
            if (c >= G_)     { s[j][0] = -FLT_MAX; s[j][2] = -FLT_MAX; }
            if (c + 1 >= G_) { s[j][1] = -FLT_MAX; s[j][3] = -FLT_MAX; }
            mx0 = fmaxf(mx0, fmaxf(s[j][0], s[j][1]));
            mx1 = fmaxf(mx1, fmaxf(s[j][2], s[j][3]));
        }
        mx0 = fmaxf(mx0, __shfl_xor_sync(0xffffffffu, mx0, 1));
        mx0 = fmaxf(mx0, __shfl_xor_sync(0xffffffffu, mx0, 2));
        mx1 = fmaxf(mx1, __shfl_xor_sync(0xffffffffu, mx1, 1));
        mx1 = fmaxf(mx1, __shfl_xor_sync(0xffffffffu, mx1, 2));
        float mn0 = fmaxf(m0v, mx0), mn1 = fmaxf(m1v, mx1);
        float a0 = __expf(m0v - mn0), a1 = __expf(m1v - mn1);
        m0v = mn0; m1v = mn1;
        #pragma unroll
        for (int j = 0; j < 8; j++) {
            o[j][0] *= a0; o[j][1] *= a0; o[j][2] *= a1; o[j][3] *= a1;
        }

        float ps0 = 0.f, ps1 = 0.f;
        #pragma unroll
        for (int j = 0; j < 8; j++) {
            s[j][0] = __expf(s[j][0] - mn0);
            s[j][1] = __expf(s[j][1] - mn0);
            s[j][2] = __expf(s[j][2] - mn1);
            s[j][3] = __expf(s[j][3] - mn1);
            ps0 += s[j][0] + s[j][1];
            ps1 += s[j][2] + s[j][3];
        }
        ps0 += __shfl_xor_sync(0xffffffffu, ps0, 1);
        ps0 += __shfl_xor_sync(0xffffffffu, ps0, 2);
        ps1 += __shfl_xor_sync(0xffffffffu, ps1, 1);
        ps1 += __shfl_xor_sync(0xffffffffu, ps1, 2);
        l0 = l0 * a0 + ps0;
        l1 = l1 * a1 + ps1;

        #pragma unroll
        for (int kbq = 0; kbq < 4; kbq++) {
            unsigned af[4];
            af[0] = pack_bf16(s[2 * kbq][0],     s[2 * kbq][1]);
            af[1] = pack_bf16(s[2 * kbq][2],     s[2 * kbq][3]);
            af[2] = pack_bf16(s[2 * kbq + 1][0], s[2 * kbq + 1][1]);
            af[3] = pack_bf16(s[2 * kbq + 1][2], s[2 * kbq + 1][3]);
            #pragma unroll
            for (int j = 0; j < 8; j++) {
                uint2 vv = *(const uint2*)&Vt[(j * 8 + g) * LDVT + kbq * 8 + 2 * r];
                unsigned bfr[2] = {vv.x, vv.y};
                mma_bf16(o[j], af, bfr);
            }
        }
    }

    float inv0 = qv0 ? 1.f / l0 : 0.f;
    float inv1 = qv1 ? 1.f / l1 : 0.f;
    #pragma unroll
    for (int j = 0; j < 8; j++) {
        int c = h * DH_ + j * 8 + 2 * r;
        if (qv0) *(unsigned*)&attH[((long)b * G_ + qrow0) * C_ + c] =
            pack_bf16(o[j][0] * inv0, o[j][1] * inv0);
        if (qv1) *(unsigned*)&attH[((long)b * G_ + qrow1) * C_ + c] =
            pack_bf16(o[j][2] * inv1, o[j][3] * inv1);
    }
}

// ---------------- sorted-segment max+mean (M=1024 segments) ------------------
__global__ void seg3d_kernel(const int* __restrict__ sci, const int* __restrict__ segid)
{
    const float* feat = g_scratch + O_FEAT;
    float* t3 = g_scratch + O_T3D;
    int s = blockIdx.x;
    __shared__ int sh[2];
    if (threadIdx.x < 2) {
        int target = s + threadIdx.x;
        int lo = 0, hi = NPT_;
        while (lo < hi) { int mid = (lo + hi) >> 1; if (segid[mid] < target) lo = mid + 1; else hi = mid; }
        sh[threadIdx.x] = lo;
    }
    __syncthreads();
    int lo = sh[0], hi = sh[1];
    int t = threadIdx.x;
    float mx[3] = {-FLT_MAX, -FLT_MAX, -FLT_MAX};
    float sm[3] = {0, 0, 0};
    for (int r = lo; r < hi; r++) {
        int n = sci[r];
        const float* f = feat + (long)n * C_;
        #pragma unroll
        for (int j = 0; j < 3; j++) {
            float v = f[t + j * 128];
            mx[j] = fmaxf(mx[j], v);
            sm[j] += v;
        }
    }
    float cnt = (float)(hi - lo);
    float invc = 1.f / fmaxf(cnt, 1.f);
    #pragma unroll
    for (int j = 0; j < 3; j++) {
        float m_ = (hi > lo) ? mx[j] : 0.f;
        t3[(long)s * C_ + t + j * 128] = m_ + sm[j] * invc;
    }
}

// ---------------- CSR build for NS x 1536 segments ----------------
__global__ void zero_cnt_kernel()
{
    int i = blockIdx.x * 256 + threadIdx.x;
    if (i < NSEGT_) ((int*)(g_scratch + O_CNT))[i] = 0;
}

__global__ void cnt_kernel(const int* __restrict__ fgi)
{
    int i = blockIdx.x * 256 + threadIdx.x;
    if (i < NS_ * NPT_)
        atomicAdd((int*)(g_scratch + O_CNT) + (long)(i / NPT_) * SEG1_ + fgi[i], 1);
}

// per-branch exclusive scan: grid = NS_, 512 threads x 3 entries (SEG1_ = 1536)
__global__ void __launch_bounds__(512) scan_kernel()
{
    int z = blockIdx.x, t = threadIdx.x;
    const int* cnt = (const int*)(g_scratch + O_CNT) + (long)z * SEG1_;
    int* off = (int*)(g_scratch + O_OFF) + (long)z * SEG1_;
    int* cur = (int*)(g_scratch + O_CUR) + (long)z * SEG1_;
    int base = t * 3;
    int v0 = cnt[base], v1 = cnt[base + 1], v2 = cnt[base + 2];
    int tot = v0 + v1 + v2;
    int lane = t & 31, warp = t >> 5;    // 16 warps
    int inc = tot;
    #pragma unroll
    for (int o2 = 1; o2 < 32; o2 <<= 1) {
        int x = __shfl_up_sync(0xffffffffu, inc, o2);
        if (lane >= o2) inc += x;
    }
    __shared__ int ws[16];
    if (lane == 31) ws[warp] = inc;
    __syncthreads();
    if (warp == 0) {
        int wv = (lane < 16) ? ws[lane] : 0;
        int wi = wv;
        #pragma unroll
        for (int o2 = 1; o2 < 16; o2 <<= 1) {
            int x = __shfl_up_sync(0xffffffffu, wi, o2);
            if (lane >= o2) wi += x;
        }
        if (lane < 16) ws[lane] = wi - wv;
    }
    __syncthreads();
    int offv = z * NPT_ + ws[warp] + (inc - tot);
    off[base] = offv;     cur[base] = offv;     offv += v0;
    off[base + 1] = offv; cur[base + 1] = offv; offv += v1;
    off[base + 2] = offv; cur[base + 2] = offv;
}

__global__ void fill_kernel(const int* __restrict__ fgi)
{
    int i = blockIdx.x * 256 + threadIdx.x;
    if (i >= NS_ * NPT_) return;
    int s = i / NPT_, n = i - s * NPT_;
    int g = fgi[i];
    int pos = atomicAdd((int*)(g_scratch + O_CUR) + (long)s * SEG1_ + g, 1);
    ((int*)(g_scratch + O_LIST))[pos] = n;
}

// ---- gather-reduce: SUM1[z,seg,:] = max + mean over that segment's fx rows ----
__global__ void seg1d_kernel()
{
    int seg = blockIdx.x, z = blockIdx.y;
    long idx = (long)z * SEG1_ + seg;
    int lo = ((const int*)(g_scratch + O_OFF))[idx];
    int cnt = ((const int*)(g_scratch + O_CNT))[idx];
    const int* list = (const int*)(g_scratch + O_LIST);
    const float* fx = g_scratch + O_FX + (long)z * NPT_ * C_;
    int t = threadIdx.x;
    float mx[3] = {-FLT_MAX, -FLT_MAX, -FLT_MAX};
    float sm[3] = {0, 0, 0};
    for (int r = 0; r < cnt; r++) {
        const float* f = fx + (long)list[lo + r] * C_;
        #pragma unroll
        for (int j = 0; j < 3; j++) {
            float v = f[t + j * 128];
            mx[j] = fmaxf(mx[j], v);
            sm[j] += v;
        }
    }
    float invc = 1.f / fmaxf((float)cnt, 1.f);
    float* o = g_scratch + O_SUM1 + idx * C_;
    #pragma unroll
    for (int j = 0; j < 3; j++) {
        float m_ = (cnt > 0) ? mx[j] : 0.f;
        o[t + j * 128] = m_ + sm[j] * invc;
    }
}

// ---------------- batchnorm stats (per column over rows) ----------------
__global__ void bnstats_kernel(const float* __restrict__ in, float* __restrict__ mean,
                               float* __restrict__ rstd, int rows, long inZ)
{
    int c = blockIdx.x, z = blockIdx.y;
    in += (long)z * inZ;
    float s = 0.f, q = 0.f;
    for (int r = threadIdx.x; r < rows; r += blockDim.x) {
        float v = in[(long)r * C_ + c];
        s += v; q += v * v;
    }
    #pragma unroll
    for (int o2 = 16; o2; o2 >>= 1) {
        s += __shfl_xor_sync(0xffffffffu, s, o2);
        q += __shfl_xor_sync(0xffffffffu, q, o2);
    }
    __shared__ float ss[8], qq[8];
    int w = threadIdx.x >> 5;
    if ((threadIdx.x & 31) == 0) { ss[w] = s; qq[w] = q; }
    __syncthreads();
    if (threadIdx.x == 0) {
        float S = 0.f, Q = 0.f;
        #pragma unroll
        for (int i = 0; i < 8; i++) { S += ss[i]; Q += qq[i]; }
        float m = S / rows;
        float var = Q / rows - m * m;
        mean[(long)z * C_ + c] = m;
        rstd[(long)z * C_ + c] = rsqrtf(var + 1e-5f);
    }
}

// ---------------- batchnorm apply + exact GELU ----------------
__global__ void bnapply_kernel(const float* __restrict__ in, float* __restrict__ out,
                               const float* __restrict__ mean, const float* __restrict__ rstd,
                               const float* __restrict__ gamma, const float* __restrict__ beta,
                               int rows, long gZ, long total)
{
    long i = blockIdx.x * (long)blockDim.x + threadIdx.x;
    if (i >= total) return;
    long rz = i / C_;
    int c = (int)(i - rz * C_);
    int z = (int)(rz / rows);
    float v = (in[i] - mean[(long)z * C_ + c]) * rstd[(long)z * C_ + c] * gamma[z * gZ + c] + beta[z * gZ + c];
    out[i] = v * normcdff(v);
}

// ---------------- final: gather, cosine weights, mix, write output -----------
__global__ void final_kernel(float* __restrict__ out,
                             const int* __restrict__ cluster, const int* __restrict__ fgi)
{
    int n = blockIdx.x;
    int t = threadIdx.x;
    if (n >= NPT_) {                    // cls rows
        int b = n - NPT_;
        #pragma unroll
        for (int j = 0; j < 3; j++)
            out[(long)b * G_ * C_ + t + j * 128] = g_scratch[O_X2 + (long)b * G_ * C_ + t + j * 128];
        return;
    }
    __shared__ float sm[4];
    auto bsum = [&](float v) -> float {
        #pragma unroll
        for (int o2 = 16; o2; o2 >>= 1) v += __shfl_xor_sync(0xffffffffu, v, o2);
        int w = t >> 5;
        if ((t & 31) == 0) sm[w] = v;
        __syncthreads();
        float r = sm[0] + sm[1] + sm[2] + sm[3];
        __syncthreads();
        return r;
    };
    float r3[3];
    const float* p3 = g_scratch + O_BN3D + (long)cluster[n] * C_;
    float pn3 = 0.f;
    #pragma unroll
    for (int j = 0; j < 3; j++) { r3[j] = p3[t + j * 128]; pn3 += r3[j] * r3[j]; }
    float n3sq = bsum(pn3);
    float na = fmaxf(sqrtf(n3sq), 1e-8f);

    float rs[6][3];
    float wts[6];
    float wsum = 0.f;
    for (int s = 0; s < NS_; s++) {
        const float* ps = g_scratch + O_BN1D + ((long)s * SEG1_ + fgi[(long)s * NPT_ + n]) * C_;
        float pd = 0.f, pq = 0.f;
        #pragma unroll
        for (int j = 0; j < 3; j++) {
            float v = ps[t + j * 128];
            rs[s][j] = v;
            pd += v * r3[j];
            pq += v * v;
        }
        float dot = bsum(pd);
        float nq = bsum(pq);
        float nb = fmaxf(sqrtf(nq), 1e-8f);
        float sim = dot / (na * nb);
        wts[s] = (sim + 1.f) * 0.5f;
        wsum += wts[s];
    }
    float invw = 1.f / wsum;
    long orow = (long)n + (n >> 10) + 1;
    #pragma unroll
    for (int j = 0; j < 3; j++) {
        int c = t + j * 128;
        float acc = 0.f;
        #pragma unroll
        for (int s = 0; s < NS_; s++) acc += rs[s][j] * wts[s];
        out[orow * C_ + c] = g_scratch[O_FEAT + (long)n * C_ + c] + 0.3f * acc * invw;
    }
}

// ---------------- host launch ----------------
extern "C" void kernel_launch(void* const* d_in, const int* in_sizes, int n_in,
                              void* d_out, int out_size)
{
    const float* x      = (const float*)d_in[0];
    const float* mask   = (const float*)d_in[1];
    const float* ln1_g  = (const float*)d_in[2];
    const float* ln1_b  = (const float*)d_in[3];
    const float* ln2_g  = (const float*)d_in[4];
    const float* ln2_b  = (const float*)d_in[5];
    const float* w_in   = (const float*)d_in[6];
    const float* b_in   = (const float*)d_in[7];
    const float* w_out  = (const float*)d_in[8];
    const float* b_out  = (const float*)d_in[9];
    const float* w_fc   = (const float*)d_in[10];
    const float* b_fc   = (const float*)d_in[11];
    const float* w_proj = (const float*)d_in[12];
    const float* b_proj = (const float*)d_in[13];
    const float* wa1    = (const float*)d_in[14];
    const float* ba1    = (const float*)d_in[15];
    const float* wa2    = (const float*)d_in[16];
    const float* ba2    = (const float*)d_in[17];
    const float* g3     = (const float*)d_in[18];
    const float* b3     = (const float*)d_in[19];
    const float* g1d    = (const float*)d_in[20];
    const float* b1d    = (const float*)d_in[21];
    const float* gn3    = (const float*)d_in[22];
    const float* bn3    = (const float*)d_in[23];
    const float* w_attn1= (const float*)d_in[24];
    const float* b_attn1= (const float*)d_in[25];
    const int* sci      = (const int*)d_in[26];
    const int* segid    = (const int*)d_in[27];
    const int* cluster  = (const int*)d_in[28];
    const int* fgi      = (const int*)d_in[29];
    float* out = (float*)d_out;

    float* base = nullptr;
    cudaGetSymbolAddress((void**)&base, g_scratch);

    const int MTB  = (ROWS_ + 127) / 128;   // 65
    const int MTBp = NPT_ / 128;            // 64
    const int MT64 = (ROWS_ + 63) / 64;     // 129

    // 0) independent prep: weight conversions + fold + CSR build
    convw_kernel<<<dim3((4 * C_ * C_ + 255) / 256, 4), 256>>>(w_in, w_out, w_fc, w_proj);
    foldw_kernel<<<dim3(C_, NS_), 128>>>(w_attn1, b_attn1, gn3, bn3,
                                         (__nv_bfloat16*)(base + O_WATT), base + O_BATT);
    zero_cnt_kernel<<<(NSEGT_ + 255) / 256, 256>>>();
    cnt_kernel<<<(NS_ * NPT_ + 255) / 256, 256>>>(fgi);
    scan_kernel<<<NS_, 512>>>();
    fill_kernel<<<(NS_ * NPT_ + 255) / 256, 256>>>(fgi);
    // 1) LN1 -> bf16
    ln_kernel<1><<<ROWS_, 128>>>(x, (__nv_bfloat16*)(base + O_LN), ln1_g, ln1_b);
    // 2) QKV = LN1 @ w_in^T + b_in -> bf16 (Q pre-scaled by 0.125)
    gemm_bf16<6><<<dim3((3 * C_) / 64, MTB, 1), 128>>>(
        base + O_LN, base + O_WIN, b_in, nullptr, nullptr,
        base + O_QKV, ROWS_, 3 * C_, C_, 0, 0, 0, 0, 0, 0);
    // 3) attention (bf16 in/out, 128 q rows/block)
    attn_mma_kernel<<<dim3((G_ + 127) / 128, B_ * H_), 256>>>();
    // 4) out proj + residual x  -> x1 (f32)
    gemm_bf16<3><<<dim3(C_ / 64, MTB, 1), 128>>>(
        base + O_ATT, base + O_WOUT, b_out, x, nullptr,
        base + O_X1, ROWS_, C_, C_, 0, 0, 0, 0, 0, 0);
    // 5) LN2 -> bf16
    ln_kernel<1><<<ROWS_, 128>>>(base + O_X1, (__nv_bfloat16*)(base + O_LN), ln2_g, ln2_b);
    // 6) fc + quick_gelu -> HFC bf16
    gemm_bf16<2><<<dim3(4 * C_ / 64, MTB, 1), 128>>>(
        base + O_LN, base + O_WFC, b_fc, nullptr, nullptr,
        base + O_HFC, ROWS_, 4 * C_, C_, 0, 0, 0, 0, 0, 0);
    // 7) proj (K=1536) -> XFFN f32
    gemm_bf16<1><<<dim3(C_ / 64, MTB, 1), 128>>>(
        base + O_HFC, base + O_WPROJ, b_proj, nullptr, nullptr,
        base + O_XFFN, ROWS_, C_, 4 * C_, 0, 0, 0, 0, 0, 0);
    // 8) adapter in + quick_gelu (SIMT fp32: N=48)
    gemm_nt<2><<<dim3(1, MT64, 1), 256>>>(
        base + O_XFFN, wa1, ba1, nullptr, nullptr,
        base + O_A1, ROWS_, 48, C_);
    // 9) adapter out + combine: x2 = x1 + xffn + 0.5*(a1@wa2^T + ba2) (SIMT: K=48)
    gemm_nt<5><<<dim3(C_ / 64, MT64, 1), 256>>>(
        base + O_A1, wa2, ba2, base + O_X1, base + O_XFFN,
        base + O_X2, ROWS_, C_, 48);
    // 10+11) feat(f32) = x2 minus cls rows, xhat(bf16) = layernorm(feat)
    ln_feat_kernel<<<NPT_, 128>>>();
    // 12) fx = (xhat @ W'^T + b')*mask + feat, batched over NS
    gemm_bf16<4><<<dim3(C_ / 64, MTBp, NS_), 128>>>(
        base + O_LNB, base + O_WATT, base + O_BATT, base + O_FEAT, mask,
        base + O_FX, NPT_, C_, C_,
        0, (long)C_ * C_ / 2, C_, (long)NPT_ * C_, NPT_, 0);
    // 13) sorted segment max+mean -> t3d (3d branch)
    seg3d_kernel<<<MSEG_, 128>>>(sci, segid);
    // 14) BN stats + apply(gelu) for 3d branch
    bnstats_kernel<<<dim3(C_, 1), 256>>>(base + O_T3D, base + O_MEAN3, base + O_RSTD3, MSEG_, 0);
    bnapply_kernel<<<(int)(((long)MSEG_ * C_ + 255) / 256), 256>>>(
        base + O_T3D, base + O_BN3D, base + O_MEAN3, base + O_RSTD3,
        g3, b3, MSEG_, 0, (long)MSEG_ * C_);
    // 15) CSR gather-reduce: per-(branch,segment) max+mean -> SUM1
    seg1d_kernel<<<dim3(SEG1_, NS_), 128>>>();
    // 16) BN stats + apply(gelu) for 1d branches
    bnstats_kernel<<<dim3(C_, NS_), 256>>>(base + O_SUM1, base + O_MEAN1, base + O_RSTD1,
                                           SEG1_, (long)SEG1_ * C_);
    bnapply_kernel<<<(int)(((long)NSEGT_ * C_ + 255) / 256), 256>>>(
        base + O_SUM1, base + O_BN1D, base + O_MEAN1, base + O_RSTD1,
        g1d, b1d, SEG1_, C_, (long)NSEGT_ * C_);
    // 17) final gather + cosine mix + output (incl. cls rows)
    final_kernel<<<ROWS_, 128>>>(out, cluster, fgi);
}

// round 15
// speedup vs baseline: 1.0316x; 1.0200x over previous
#include <cuda_runtime.h>
#include <cuda_bf16.h>
#include <float.h>
#include <math.h>

// ---------------- problem constants ----------------
namespace cfg {
constexpr int B_ = 8, G_ = 1025, GP_ = 1024, C_ = 384, H_ = 6, DH_ = 64;
constexpr int NS_ = 6, MSEG_ = 1024, SEG1_ = 1536;      // SEG1 = B*GRID
constexpr int NPT_ = B_ * GP_;                          // 8192 points
constexpr int ROWS_ = B_ * G_;                          // 8200 rows incl cls
constexpr int NSEGT_ = NS_ * SEG1_;                     // 9216

// scratch layout (floats; several regions hold bf16 and use half)
constexpr long O_LN   = 0;                              // bf16
constexpr long O_QKV  = O_LN   + (long)ROWS_ * C_;      // bf16
constexpr long O_ATT  = O_QKV  + (long)ROWS_ * 3 * C_;  // bf16
constexpr long O_X1   = O_ATT  + (long)ROWS_ * C_;
constexpr long O_HFC  = O_X1   + (long)ROWS_ * C_;      // bf16
constexpr long O_XFFN = O_HFC  + (long)ROWS_ * 4 * C_;
constexpr long O_A1   = O_XFFN + (long)ROWS_ * C_;
constexpr long O_X2   = O_A1   + (long)ROWS_ * 48;
constexpr long O_FEAT = O_X2   + (long)ROWS_ * C_;
constexpr long O_LNB  = O_FEAT + (long)NPT_ * C_;       // bf16
constexpr long O_FX   = O_LNB  + (long)NPT_ * C_;       // bf16 (NS*NPT*C halves)
constexpr long O_T3D  = O_FX   + (long)NS_ * NPT_ * C_ / 2;
constexpr long O_BN3D = O_T3D  + (long)MSEG_ * C_;
constexpr long O_MEAN3= O_BN3D + (long)MSEG_ * C_;
constexpr long O_RSTD3= O_MEAN3+ C_;
constexpr long O_SUM1 = O_RSTD3+ C_;
constexpr long O_BN1D = O_SUM1 + (long)NSEGT_ * C_;
constexpr long O_MEAN1= O_BN1D + (long)NSEGT_ * C_;
constexpr long O_RSTD1= O_MEAN1+ (long)NS_ * C_;
constexpr long O_WATT = O_RSTD1+ (long)NS_ * C_;
constexpr long O_BATT = O_WATT + (long)NS_ * C_ * C_;
constexpr long O_CNT  = O_BATT + (long)NS_ * C_;        // int[NSEGT]
constexpr long O_OFF  = O_CNT  + NSEGT_;                // int[NSEGT]
constexpr long O_CUR  = O_OFF  + NSEGT_;                // int[NSEGT]
constexpr long O_LIST = O_CUR  + NSEGT_;                // int[NS*NPT]
constexpr long TOTAL  = O_LIST + (long)NS_ * NPT_;
}
using namespace cfg;

__device__ __align__(16) float g_scratch[TOTAL];

// ---------------- helpers ----------------
__device__ __forceinline__ unsigned pack_bf16(float lo, float hi) {
    unsigned r;
    asm("cvt.rn.bf16x2.f32 %0, %1, %2;" : "=r"(r) : "f"(hi), "f"(lo));
    return r;
}

__device__ __forceinline__ void mma_bf16(float c[4], const unsigned a[4], const unsigned b[2]) {
    asm volatile(
        "mma.sync.aligned.m16n8k16.row.col.f32.bf16.bf16.f32 "
        "{%0,%1,%2,%3},{%4,%5,%6,%7},{%8,%9},{%0,%1,%2,%3};"
        : "+f"(c[0]), "+f"(c[1]), "+f"(c[2]), "+f"(c[3])
        : "r"(a[0]), "r"(a[1]), "r"(a[2]), "r"(a[3]), "r"(b[0]), "r"(b[1]));
}

// pair-interleave within each group of 8 pairs: (q, q+4) become adjacent words
__device__ __forceinline__ int ilv(int p) {
    return (p & ~7) | (((p & 3) << 1) | ((p >> 2) & 1));
}

// ---------------- LayerNorm (C=384, 128 threads), bf16 output ----
template<int AFFINE>
__global__ void ln_kernel(const float* __restrict__ in, __nv_bfloat16* __restrict__ out,
                          const float* __restrict__ gamma, const float* __restrict__ beta)
{
    long row = blockIdx.x;
    const float* x = in + row * C_;
    __nv_bfloat16* o = out + row * C_;
    int t = threadIdx.x;
    float v0 = x[t], v1 = x[t + 128], v2 = x[t + 256];
    float s = v0 + v1 + v2;
    float q = v0 * v0 + v1 * v1 + v2 * v2;
    __shared__ float sm[8];
    #pragma unroll
    for (int o2 = 16; o2; o2 >>= 1) {
        s += __shfl_xor_sync(0xffffffffu, s, o2);
        q += __shfl_xor_sync(0xffffffffu, q, o2);
    }
    int w = t >> 5;
    if ((t & 31) == 0) { sm[w] = s; sm[4 + w] = q; }
    __syncthreads();
    s = sm[0] + sm[1] + sm[2] + sm[3];
    q = sm[4] + sm[5] + sm[6] + sm[7];
    float mean = s * (1.f / C_);
    float var  = q * (1.f / C_) - mean * mean;
    float rstd = rsqrtf(var + 1e-5f);
    if (AFFINE) {
        o[t]       = __float2bfloat16((v0 - mean) * rstd * gamma[t]       + beta[t]);
        o[t + 128] = __float2bfloat16((v1 - mean) * rstd * gamma[t + 128] + beta[t + 128]);
        o[t + 256] = __float2bfloat16((v2 - mean) * rstd * gamma[t + 256] + beta[t + 256]);
    } else {
        o[t]       = __float2bfloat16((v0 - mean) * rstd);
        o[t + 128] = __float2bfloat16((v1 - mean) * rstd);
        o[t + 256] = __float2bfloat16((v2 - mean) * rstd);
    }
}

// ---- fused: feat(f32) = x2 minus cls rows ; xhat(bf16) = layernorm(feat) ----
__global__ void ln_feat_kernel()
{
    int n = blockIdx.x;
    long row = (long)n + (n >> 10) + 1;
    const float* x = g_scratch + O_X2 + row * C_;
    float* feat = g_scratch + O_FEAT + (long)n * C_;
    __nv_bfloat16* xhat = (__nv_bfloat16*)(g_scratch + O_LNB) + (long)n * C_;
    int t = threadIdx.x;
    float v0 = x[t], v1 = x[t + 128], v2 = x[t + 256];
    float s = v0 + v1 + v2;
    float q = v0 * v0 + v1 * v1 + v2 * v2;
    __shared__ float sm[8];
    #pragma unroll
    for (int o2 = 16; o2; o2 >>= 1) {
        s += __shfl_xor_sync(0xffffffffu, s, o2);
        q += __shfl_xor_sync(0xffffffffu, q, o2);
    }
    int w = t >> 5;
    if ((t & 31) == 0) { sm[w] = s; sm[4 + w] = q; }
    __syncthreads();
    s = sm[0] + sm[1] + sm[2] + sm[3];
    q = sm[4] + sm[5] + sm[6] + sm[7];
    float mean = s * (1.f / C_);
    float var  = q * (1.f / C_) - mean * mean;
    float rstd = rsqrtf(var + 1e-5f);
    feat[t]       = v0; xhat[t]       = __float2bfloat16((v0 - mean) * rstd);
    feat[t + 128] = v1; xhat[t + 128] = __float2bfloat16((v1 - mean) * rstd);
    feat[t + 256] = v2; xhat[t + 256] = __float2bfloat16((v2 - mean) * rstd);
}

// ---- fold LN3 affine into w_attn1: W'[n][k]=W[n][k]*g[k], b' = b + W b3 ----
__global__ void foldw_kernel(const float* __restrict__ w, const float* __restrict__ bw,
                             const float* __restrict__ g, const float* __restrict__ b,
                             float* __restrict__ wout, float* __restrict__ bout)
{
    int n = blockIdx.x, z = blockIdx.y, t = threadIdx.x;
    const float* wr = w + ((long)z * C_ + n) * C_;
    const float* gz = g + (long)z * C_;
    const float* bz = b + (long)z * C_;
    float* wo = wout + ((long)z * C_ + n) * C_;
    float acc = 0.f;
    for (int c = t; c < C_; c += 128) {
        float wv = wr[c];
        wo[c] = wv * gz[c];
        acc += wv * bz[c];
    }
    #pragma unroll
    for (int o2 = 16; o2; o2 >>= 1) acc += __shfl_xor_sync(0xffffffffu, acc, o2);
    __shared__ float sr[4];
    if ((t & 31) == 0) sr[t >> 5] = acc;
    __syncthreads();
    if (t == 0) bout[(long)z * C_ + n] = sr[0] + sr[1] + sr[2] + sr[3] + bw[(long)z * C_ + n];
}

// ---------------- BF16 tensor-core NT GEMM: C[m,n] = sum_k A[m,k]*W[n,k] -----
// A operand is bf16 in gmem (uint pairs); W is f32 (packed in sts).
// MODE 1: +bias ; 2: quick_gelu(+bias) -> bf16 out ; 3: +bias + R1 ;
// MODE 4: (+bias)*mrow[m]+R1 -> bf16 out ; 6: bf16 out, Q cols pre-scaled 0.125
template<int MODE>
__global__ void __launch_bounds__(128) gemm_bf16(
    const void* __restrict__ Av, const float* __restrict__ W,
    const float* __restrict__ bias, const float* __restrict__ R1,
    const float* __restrict__ mrow, float* __restrict__ Co,
    int Mr, int Nc, int K,
    long aZ, long wZ, long bZ, long cZ, long mZ, long r1Z)
{
    constexpr int BM = 128, BN = 64, BK = 16, LD = 12;   // LD in uint32 (bf16 pairs)
    __shared__ unsigned As[2][BM * LD];
    __shared__ unsigned Bs[2][BN * LD];
    int z = blockIdx.z;
    const unsigned* A = (const unsigned*)Av + (long)z * aZ;   // aZ in uints
    const int KW = K / 2;                                      // uints per A row
    W += (long)z * wZ; bias += (long)z * bZ; Co += (long)z * cZ;
    if (MODE == 4) mrow += (long)z * mZ;
    if (MODE == 3 || MODE == 4) R1 += (long)z * r1Z;
    int m0 = blockIdx.y * BM, n0 = blockIdx.x * BN;
    int tid = threadIdx.x;

    int arow = tid >> 2;            // 0..31
    int c4 = tid & 3;               // float4 index within the 16-k stage
    int acol = c4 * 4;
    int p0 = (c4 < 2) ? 4 * c4 : 4 * c4 - 7;    // interleaved pair position

    const unsigned* Ap[4]; bool am[4];
    #pragma unroll
    for (int i = 0; i < 4; i++) {
        int gm = m0 + arow + 32 * i;
        am[i] = gm < Mr;
        Ap[i] = A + (long)gm * KW + c4 * 2;
    }
    const float* Wp0 = W + (long)(n0 + arow) * K + acol;
    const float* Wp1 = W + (long)(n0 + arow + 32) * K + acol;

    uint2 ua[4]; float4 lb[2];
    auto ldg = [&](int k0) {
        int kw = k0 / 2;
        #pragma unroll
        for (int i = 0; i < 4; i++)
            ua[i] = am[i] ? *(const uint2*)(Ap[i] + kw) : make_uint2(0, 0);
        lb[0] = *(const float4*)(Wp0 + k0);
        lb[1] = *(const float4*)(Wp1 + k0);
    };
    auto sts = [&](int buf) {
        #pragma unroll
        for (int i = 0; i < 4; i++) {
            unsigned* p = &As[buf][(arow + 32 * i) * LD + p0];
            p[0] = ua[i].x;
            p[2] = ua[i].y;
        }
        #pragma unroll
        for (int j = 0; j < 2; j++) {
            unsigned* p = &Bs[buf][(arow + 32 * j) * LD + p0];
            p[0] = pack_bf16(lb[j].x, lb[j].y);
            p[2] = pack_bf16(lb[j].z, lb[j].w);
        }
    };

    int warp = tid >> 5, lane = tid & 31;
    int wm = (warp >> 1) * 64, wn = (warp & 1) * 32;
    int g = lane >> 2, r = lane & 3;

    float acc[4][4][4] = {};

    ldg(0);
    sts(0);
    __syncthreads();

    const int nstage = K / BK;
    int buf = 0;
    for (int s = 0; s < nstage; s++) {
        if (s + 1 < nstage) ldg((s + 1) * BK);
        unsigned af[4][4], bf[4][2];
        #pragma unroll
        for (int i = 0; i < 4; i++) {
            int mr_ = wm + 16 * i + g;
            uint2 va = *(const uint2*)&As[buf][mr_ * LD + 2 * r];
            uint2 vb = *(const uint2*)&As[buf][(mr_ + 8) * LD + 2 * r];
            af[i][0] = va.x; af[i][2] = va.y;
            af[i][1] = vb.x; af[i][3] = vb.y;
        }
        #pragma unroll
        for (int j = 0; j < 4; j++) {
            uint2 w2 = *(const uint2*)&Bs[buf][(wn + 8 * j + g) * LD + 2 * r];
            bf[j][0] = w2.x; bf[j][1] = w2.y;
        }
        #pragma unroll
        for (int i = 0; i < 4; i++)
            #pragma unroll
            for (int j = 0; j < 4; j++)
                mma_bf16(acc[i][j], af[i], bf[j]);
        if (s + 1 < nstage) sts(buf ^ 1);
        __syncthreads();
        buf ^= 1;
    }

    // epilogue
    __nv_bfloat16* CoH = (__nv_bfloat16*)Co;
    #pragma unroll
    for (int i = 0; i < 4; i++) {
        #pragma unroll
        for (int half = 0; half < 2; half++) {
            int m = m0 + wm + 16 * i + g + 8 * half;
            if (m >= Mr) continue;
            float msk = (MODE == 4) ? mrow[m] : 0.f;
            #pragma unroll
            for (int j = 0; j < 4; j++) {
                int n = n0 + wn + 8 * j + 2 * r;
                float v0 = acc[i][j][2 * half]     + bias[n];
                float v1 = acc[i][j][2 * half + 1] + bias[n + 1];
                long idx = (long)m * Nc + n;
                if (MODE == 6) {
                    float sc = (n < C_) ? 0.125f : 1.f;
                    *(unsigned*)(CoH + idx) = pack_bf16(v0 * sc, v1 * sc);
                    continue;
                }
                if (MODE == 2) {
                    *(unsigned*)(CoH + idx) = pack_bf16(
                        v0 / (1.f + __expf(-1.702f * v0)),
                        v1 / (1.f + __expf(-1.702f * v1)));
                    continue;
                }
                if (MODE == 4) {
                    float fx0 = v0 * msk + R1[idx];
                    float fx1 = v1 * msk + R1[idx + 1];
                    *(unsigned*)(CoH + idx) = pack_bf16(fx0, fx1);
                    continue;
                }
                float r0, r1v;
                if (MODE == 1)      { r0 = v0; r1v = v1; }
                else                { r0 = v0 + R1[idx]; r1v = v1 + R1[idx + 1]; }
                *(float2*)(Co + idx) = make_float2(r0, r1v);
            }
        }
    }
}

// ---------------- SIMT fallback GEMM (adapter shapes, f32) ----------------
// MODE 2: quick_gelu(+bias) ; 5: R1 + R2 + 0.5*(+bias)
template<int MODE>
__global__ void __launch_bounds__(256) gemm_nt(
    const float* __restrict__ A, const float* __restrict__ W,
    const float* __restrict__ bias, const float* __restrict__ R1,
    const float* __restrict__ R2, float* __restrict__ Co,
    int Mr, int Nc, int K)
{
    __shared__ float As[16][64];
    __shared__ float Ws[16][64];
    int m0 = blockIdx.y * 64, n0 = blockIdx.x * 64;
    int tid = threadIdx.x;
    int lr = tid >> 2, lk = (tid & 3) << 2;
    int ty = tid >> 4, tx = tid & 15;
    float acc[4][4] = {};
    for (int k0 = 0; k0 < K; k0 += 16) {
        float4 va = make_float4(0, 0, 0, 0), vw = make_float4(0, 0, 0, 0);
        int gm = m0 + lr;
        if (gm < Mr) va = *(const float4*)(A + (long)gm * K + (k0 + lk));
        int gn = n0 + lr;
        if (gn < Nc) vw = *(const float4*)(W + (long)gn * K + (k0 + lk));
        __syncthreads();
        As[lk][lr] = va.x; As[lk + 1][lr] = va.y; As[lk + 2][lr] = va.z; As[lk + 3][lr] = va.w;
        Ws[lk][lr] = vw.x; Ws[lk + 1][lr] = vw.y; Ws[lk + 2][lr] = vw.z; Ws[lk + 3][lr] = vw.w;
        __syncthreads();
        #pragma unroll
        for (int kk = 0; kk < 16; kk++) {
            float4 a4 = *(const float4*)&As[kk][ty << 2];
            float4 b4 = *(const float4*)&Ws[kk][tx << 2];
            acc[0][0] += a4.x * b4.x; acc[0][1] += a4.x * b4.y; acc[0][2] += a4.x * b4.z; acc[0][3] += a4.x * b4.w;
            acc[1][0] += a4.y * b4.x; acc[1][1] += a4.y * b4.y; acc[1][2] += a4.y * b4.z; acc[1][3] += a4.y * b4.w;
            acc[2][0] += a4.z * b4.x; acc[2][1] += a4.z * b4.y; acc[2][2] += a4.z * b4.z; acc[2][3] += a4.z * b4.w;
            acc[3][0] += a4.w * b4.x; acc[3][1] += a4.w * b4.y; acc[3][2] += a4.w * b4.z; acc[3][3] += a4.w * b4.w;
        }
    }
    #pragma unroll
    for (int i = 0; i < 4; i++) {
        int m = m0 + (ty << 2) + i;
        if (m >= Mr) continue;
        #pragma unroll
        for (int j = 0; j < 4; j++) {
            int n = n0 + (tx << 2) + j;
            if (n >= Nc) continue;
            float v = acc[i][j] + bias[n];
            long idx = (long)m * Nc + n;
            float rr;
            if (MODE == 2) rr = v / (1.f + __expf(-1.702f * v));
            else           rr = R1[idx] + R2[idx] + 0.5f * v;
            Co[idx] = rr;
        }
    }
}

// ---------------- bf16 tensor-core flash attention ----------------
// 128 q-rows per block (8 warps x m16), 64-key tiles, dh=64.
__global__ void __launch_bounds__(256, 2) attn_mma_kernel()
{
    constexpr int LDK = 36, LDVT = 36;   // words (bf16 pairs), 32 + pad
    __shared__ unsigned Ks[64 * LDK];
    __shared__ unsigned Vt[64 * LDVT];
    const unsigned* qkv = (const unsigned*)(g_scratch + O_QKV);
    const int RW = 3 * C_ / 2;
    __nv_bfloat16* attH = (__nv_bfloat16*)(g_scratch + O_ATT);
    int bh = blockIdx.y;
    int b = bh / H_, h = bh % H_;
    int q0 = blockIdx.x * 128;
    const unsigned* qb = qkv + (long)b * G_ * RW + h * (DH_ / 2);
    const unsigned* kb = qb + C_ / 2;
    const unsigned* vb = qb + C_;
    int tid = threadIdx.x, warp = tid >> 5, lane = tid & 31;
    int g = lane >> 2, r = lane & 3;

    unsigned qf[4][4];
    int qrow0 = q0 + warp * 16 + g;
    int qrow1 = qrow0 + 8;
    bool qv0 = qrow0 < G_, qv1 = qrow1 < G_;
    const unsigned* qp0 = qb + (long)qrow0 * RW;
    const unsigned* qp1 = qb + (long)qrow1 * RW;
    #pragma unroll
    for (int kbq = 0; kbq < 4; kbq++) {
        int u0 = kbq * 8 + r;
        qf[kbq][0] = qv0 ? qp0[u0]     : 0u;
        qf[kbq][1] = qv1 ? qp1[u0]     : 0u;
        qf[kbq][2] = qv0 ? qp0[u0 + 4] : 0u;
        qf[kbq][3] = qv1 ? qp1[u0 + 4] : 0u;
    }

    float o[8][4] = {};
    float m0v = -FLT_MAX, m1v = -FLT_MAX, l0 = 0.f, l1 = 0.f;
    unsigned short* VtS = (unsigned short*)Vt;

    for (int n0 = 0; n0 < G_; n0 += 64) {
        __syncthreads();
        #pragma unroll
        for (int it = 0; it < 4; it++) {
            int i = tid + it * 256;
            int key = i >> 4, c4 = i & 15;
            int gk = n0 + key;
            uint2 kv = make_uint2(0, 0), vv = make_uint2(0, 0);
            if (gk < G_) {
                kv = *(const uint2*)(kb + (long)gk * RW + c4 * 2);
                vv = *(const uint2*)(vb + (long)gk * RW + c4 * 2);
            }
            Ks[key * LDK + ilv(2 * c4)]     = kv.x;
            Ks[key * LDK + ilv(2 * c4 + 1)] = kv.y;
            int vword = ilv(key >> 1);
            int vhalf = key & 1;
            VtS[((4 * c4 + 0) * LDVT + vword) * 2 + vhalf] = (unsigned short)(vv.x & 0xffffu);
            VtS[((4 * c4 + 1) * LDVT + vword) * 2 + vhalf] = (unsigned short)(vv.x >> 16);
            VtS[((4 * c4 + 2) * LDVT + vword) * 2 + vhalf] = (unsigned short)(vv.y & 0xffffu);
            VtS[((4 * c4 + 3) * LDVT + vword) * 2 + vhalf] = (unsigned short)(vv.y >> 16);
        }
        __syncthreads();

        float s[8][4] = {};
        #pragma unroll
        for (int kbq = 0; kbq < 4; kbq++) {
            #pragma unroll
            for (int j = 0; j < 8; j++) {
                uint2 bv = *(const uint2*)&Ks[(j * 8 + g) * LDK + kbq * 8 + 2 * r];
                unsigned bfr[2] = {bv.x, bv.y};
                mma_bf16(s[j], qf[kbq], bfr);
            }
        }
        float mx0 = -FLT_MAX, mx1 = -FLT_MAX;
        #pragma unroll
        for (int j = 0; j < 8; j++) {
            int c = n0 + j * 8 + 2 * r;
            if (c >= G_)     { s[j][0] = -FLT_MAX; s[j][2] = -FLT_MAX; }
            if (c + 1 >= G_) { s[j][1] = -FLT_MAX; s[j][3] = -FLT_MAX; }
            mx0 = fmaxf(mx0, fmaxf(s[j][0], s[j][1]));
            mx1 = fmaxf(mx1, fmaxf(s[j][2], s[j][3]));
        }
        mx0 = fmaxf(mx0, __shfl_xor_sync(0xffffffffu, mx0, 1));
        mx0 = fmaxf(mx0, __shfl_xor_sync(0xffffffffu, mx0, 2));
        mx1 = fmaxf(mx1, __shfl_xor_sync(0xffffffffu, mx1, 1));
        mx1 = fmaxf(mx1, __shfl_xor_sync(0xffffffffu, mx1, 2));
        float mn0 = fmaxf(m0v, mx0), mn1 = fmaxf(m1v, mx1);
        float a0 = __expf(m0v - mn0), a1 = __expf(m1v - mn1);
        m0v = mn0; m1v = mn1;
        #pragma unroll
        for (int j = 0; j < 8; j++) {
            o[j][0] *= a0; o[j][1] *= a0; o[j][2] *= a1; o[j][3] *= a1;
        }

        float ps0 = 0.f, ps1 = 0.f;
        #pragma unroll
        for (int j = 0; j < 8; j++) {
            s[j][0] = __expf(s[j][0] - mn0);
            s[j][1] = __expf(s[j][1] - mn0);
            s[j][2] = __expf(s[j][2] - mn1);
            s[j][3] = __expf(s[j][3] - mn1);
            ps0 += s[j][0] + s[j][1];
            ps1 += s[j][2] + s[j][3];
        }
        ps0 += __shfl_xor_sync(0xffffffffu, ps0, 1);
        ps0 += __shfl_xor_sync(0xffffffffu, ps0, 2);
        ps1 += __shfl_xor_sync(0xffffffffu, ps1, 1);
        ps1 += __shfl_xor_sync(0xffffffffu, ps1, 2);
        l0 = l0 * a0 + ps0;
        l1 = l1 * a1 + ps1;

        #pragma unroll
        for (int kbq = 0; kbq < 4; kbq++) {
            unsigned af[4];
            af[0] = pack_bf16(s[2 * kbq][0],     s[2 * kbq][1]);
            af[1] = pack_bf16(s[2 * kbq][2],     s[2 * kbq][3]);
            af[2] = pack_bf16(s[2 * kbq + 1][0], s[2 * kbq + 1][1]);
            af[3] = pack_bf16(s[2 * kbq + 1][2], s[2 * kbq + 1][3]);
            #pragma unroll
            for (int j = 0; j < 8; j++) {
                uint2 vv = *(const uint2*)&Vt[(j * 8 + g) * LDVT + kbq * 8 + 2 * r];
                unsigned bfr[2] = {vv.x, vv.y};
                mma_bf16(o[j], af, bfr);
            }
        }
    }

    float inv0 = qv0 ? 1.f / l0 : 0.f;
    float inv1 = qv1 ? 1.f / l1 : 0.f;
    #pragma unroll
    for (int j = 0; j < 8; j++) {
        int c = h * DH_ + j * 8 + 2 * r;
        if (qv0) *(unsigned*)&attH[((long)b * G_ + qrow0) * C_ + c] =
            pack_bf16(o[j][0] * inv0, o[j][1] * inv0);
        if (qv1) *(unsigned*)&attH[((long)b * G_ + qrow1) * C_ + c] =
            pack_bf16(o[j][2] * inv1, o[j][3] * inv1);
    }
}

// ---------------- sorted-segment max+mean (M=1024 segments) ------------------
__global__ void seg3d_kernel(const int* __restrict__ sci, const int* __restrict__ segid)
{
    const float* feat = g_scratch + O_FEAT;
    float* t3 = g_scratch + O_T3D;
    int s = blockIdx.x;
    __shared__ int sh[2];
    if (threadIdx.x < 2) {
        int target = s + threadIdx.x;
        int lo = 0, hi = NPT_;
        while (lo < hi) { int mid = (lo + hi) >> 1; if (segid[mid] < target) lo = mid + 1; else hi = mid; }
        sh[threadIdx.x] = lo;
    }
    __syncthreads();
    int lo = sh[0], hi = sh[1];
    int t = threadIdx.x;
    float mx[3] = {-FLT_MAX, -FLT_MAX, -FLT_MAX};
    float sm[3] = {0, 0, 0};
    for (int r = lo; r < hi; r++) {
        int n = sci[r];
        const float* f = feat + (long)n * C_;
        #pragma unroll
        for (int j = 0; j < 3; j++) {
            float v = f[t + j * 128];
            mx[j] = fmaxf(mx[j], v);
            sm[j] += v;
        }
    }
    float cnt = (float)(hi - lo);
    float invc = 1.f / fmaxf(cnt, 1.f);
    #pragma unroll
    for (int j = 0; j < 3; j++) {
        float m_ = (hi > lo) ? mx[j] : 0.f;
        t3[(long)s * C_ + t + j * 128] = m_ + sm[j] * invc;
    }
}

// ---------------- CSR build for NS x 1536 segments ----------------
__global__ void zero_cnt_kernel()
{
    int i = blockIdx.x * 256 + threadIdx.x;
    if (i < NSEGT_) ((int*)(g_scratch + O_CNT))[i] = 0;
}

__global__ void cnt_kernel(const int* __restrict__ fgi)
{
    int i = blockIdx.x * 256 + threadIdx.x;
    if (i < NS_ * NPT_)
        atomicAdd((int*)(g_scratch + O_CNT) + (long)(i / NPT_) * SEG1_ + fgi[i], 1);
}

// per-branch exclusive scan: grid = NS_, 512 threads x 3 entries (SEG1_ = 1536)
__global__ void __launch_bounds__(512) scan_kernel()
{
    int z = blockIdx.x, t = threadIdx.x;
    const int* cnt = (const int*)(g_scratch + O_CNT) + (long)z * SEG1_;
    int* off = (int*)(g_scratch + O_OFF) + (long)z * SEG1_;
    int* cur = (int*)(g_scratch + O_CUR) + (long)z * SEG1_;
    int base = t * 3;
    int v0 = cnt[base], v1 = cnt[base + 1], v2 = cnt[base + 2];
    int tot = v0 + v1 + v2;
    int lane = t & 31, warp = t >> 5;    // 16 warps
    int inc = tot;
    #pragma unroll
    for (int o2 = 1; o2 < 32; o2 <<= 1) {
        int x = __shfl_up_sync(0xffffffffu, inc, o2);
        if (lane >= o2) inc += x;
    }
    __shared__ int ws[16];
    if (lane == 31) ws[warp] = inc;
    __syncthreads();
    if (warp == 0) {
        int wv = (lane < 16) ? ws[lane] : 0;
        int wi = wv;
        #pragma unroll
        for (int o2 = 1; o2 < 16; o2 <<= 1) {
            int x = __shfl_up_sync(0xffffffffu, wi, o2);
            if (lane >= o2) wi += x;
        }
        if (lane < 16) ws[lane] = wi - wv;
    }
    __syncthreads();
    int offv = z * NPT_ + ws[warp] + (inc - tot);
    off[base] = offv;     cur[base] = offv;     offv += v0;
    off[base + 1] = offv; cur[base + 1] = offv; offv += v1;
    off[base + 2] = offv; cur[base + 2] = offv;
}

__global__ void fill_kernel(const int* __restrict__ fgi)
{
    int i = blockIdx.x * 256 + threadIdx.x;
    if (i >= NS_ * NPT_) return;
    int s = i / NPT_, n = i - s * NPT_;
    int g = fgi[i];
    int pos = atomicAdd((int*)(g_scratch + O_CUR) + (long)s * SEG1_ + g, 1);
    ((int*)(g_scratch + O_LIST))[pos] = n;
}

// ---- gather-reduce (bf16 FX): SUM1[z,seg,:] = max + mean over segment rows ----
__global__ void seg1d_kernel()
{
    int seg = blockIdx.x, z = blockIdx.y;
    long idx = (long)z * SEG1_ + seg;
    int lo = ((const int*)(g_scratch + O_OFF))[idx];
    int cnt = ((const int*)(g_scratch + O_CNT))[idx];
    const int* list = (const int*)(g_scratch + O_LIST);
    const __nv_bfloat16* fx = (const __nv_bfloat16*)(g_scratch + O_FX) + (long)z * NPT_ * C_;
    int t = threadIdx.x;
    float mx[3] = {-FLT_MAX, -FLT_MAX, -FLT_MAX};
    float sm[3] = {0, 0, 0};
    for (int r = 0; r < cnt; r++) {
        const __nv_bfloat16* f = fx + (long)list[lo + r] * C_;
        #pragma unroll
        for (int j = 0; j < 3; j++) {
            float v = __bfloat162float(f[t + j * 128]);
            mx[j] = fmaxf(mx[j], v);
            sm[j] += v;
        }
    }
    float invc = 1.f / fmaxf((float)cnt, 1.f);
    float* o = g_scratch + O_SUM1 + idx * C_;
    #pragma unroll
    for (int j = 0; j < 3; j++) {
        float m_ = (cnt > 0) ? mx[j] : 0.f;
        o[t + j * 128] = m_ + sm[j] * invc;
    }
}

// ---------------- batchnorm stats (per column over rows) ----------------
__global__ void bnstats_kernel(const float* __restrict__ in, float* __restrict__ mean,
                               float* __restrict__ rstd, int rows, long inZ)
{
    int c = blockIdx.x, z = blockIdx.y;
    in += (long)z * inZ;
    float s = 0.f, q = 0.f;
    for (int r = threadIdx.x; r < rows; r += blockDim.x) {
        float v = in[(long)r * C_ + c];
        s += v; q += v * v;
    }
    #pragma unroll
    for (int o2 = 16; o2; o2 >>= 1) {
        s += __shfl_xor_sync(0xffffffffu, s, o2);
        q += __shfl_xor_sync(0xffffffffu, q, o2);
    }
    __shared__ float ss[8], qq[8];
    int w = threadIdx.x >> 5;
    if ((threadIdx.x & 31) == 0) { ss[w] = s; qq[w] = q; }
    __syncthreads();
    if (threadIdx.x == 0) {
        float S = 0.f, Q = 0.f;
        #pragma unroll
        for (int i = 0; i < 8; i++) { S += ss[i]; Q += qq[i]; }
        float m = S / rows;
        float var = Q / rows - m * m;
        mean[(long)z * C_ + c] = m;
        rstd[(long)z * C_ + c] = rsqrtf(var + 1e-5f);
    }
}

// ---------------- batchnorm apply + exact GELU ----------------
__global__ void bnapply_kernel(const float* __restrict__ in, float* __restrict__ out,
                               const float* __restrict__ mean, const float* __restrict__ rstd,
                               const float* __restrict__ gamma, const float* __restrict__ beta,
                               int rows, long gZ, long total)
{
    long i = blockIdx.x * (long)blockDim.x + threadIdx.x;
    if (i >= total) return;
    long rz = i / C_;
    int c = (int)(i - rz * C_);
    int z = (int)(rz / rows);
    float v = (in[i] - mean[(long)z * C_ + c]) * rstd[(long)z * C_ + c] * gamma[z * gZ + c] + beta[z * gZ + c];
    out[i] = v * normcdff(v);
}

// ---------------- final: gather, cosine weights, mix, write output -----------
__global__ void final_kernel(float* __restrict__ out,
                             const int* __restrict__ cluster, const int* __restrict__ fgi)
{
    int n = blockIdx.x;
    int t = threadIdx.x;
    if (n >= NPT_) {                    // cls rows
        int b = n - NPT_;
        #pragma unroll
        for (int j = 0; j < 3; j++)
            out[(long)b * G_ * C_ + t + j * 128] = g_scratch[O_X2 + (long)b * G_ * C_ + t + j * 128];
        return;
    }
    __shared__ float sm[4];
    auto bsum = [&](float v) -> float {
        #pragma unroll
        for (int o2 = 16; o2; o2 >>= 1) v += __shfl_xor_sync(0xffffffffu, v, o2);
        int w = t >> 5;
        if ((t & 31) == 0) sm[w] = v;
        __syncthreads();
        float r = sm[0] + sm[1] + sm[2] + sm[3];
        __syncthreads();
        return r;
    };
    float r3[3];
    const float* p3 = g_scratch + O_BN3D + (long)cluster[n] * C_;
    float pn3 = 0.f;
    #pragma unroll
    for (int j = 0; j < 3; j++) { r3[j] = p3[t + j * 128]; pn3 += r3[j] * r3[j]; }
    float n3sq = bsum(pn3);
    float na = fmaxf(sqrtf(n3sq), 1e-8f);

    float rs[6][3];
    float wts[6];
    float wsum = 0.f;
    for (int s = 0; s < NS_; s++) {
        const float* ps = g_scratch + O_BN1D + ((long)s * SEG1_ + fgi[(long)s * NPT_ + n]) * C_;
        float pd = 0.f, pq = 0.f;
        #pragma unroll
        for (int j = 0; j < 3; j++) {
            float v = ps[t + j * 128];
            rs[s][j] = v;
            pd += v * r3[j];
            pq += v * v;
        }
        float dot = bsum(pd);
        float nq = bsum(pq);
        float nb = fmaxf(sqrtf(nq), 1e-8f);
        float sim = dot / (na * nb);
        wts[s] = (sim + 1.f) * 0.5f;
        wsum += wts[s];
    }
    float invw = 1.f / wsum;
    long orow = (long)n + (n >> 10) + 1;
    #pragma unroll
    for (int j = 0; j < 3; j++) {
        int c = t + j * 128;
        float acc = 0.f;
        #pragma unroll
        for (int s = 0; s < NS_; s++) acc += rs[s][j] * wts[s];
        out[orow * C_ + c] = g_scratch[O_FEAT + (long)n * C_ + c] + 0.3f * acc * invw;
    }
}

// ---------------- host launch ----------------
extern "C" void kernel_launch(void* const* d_in, const int* in_sizes, int n_in,
                              void* d_out, int out_size)
{
    const float* x      = (const float*)d_in[0];
    const float* mask   = (const float*)d_in[1];
    const float* ln1_g  = (const float*)d_in[2];
    const float* ln1_b  = (const float*)d_in[3];
    const float* ln2_g  = (const float*)d_in[4];
    const float* ln2_b  = (const float*)d_in[5];
    const float* w_in   = (const float*)d_in[6];
    const float* b_in   = (const float*)d_in[7];
    const float* w_out  = (const float*)d_in[8];
    const float* b_out  = (const float*)d_in[9];
    const float* w_fc   = (const float*)d_in[10];
    const float* b_fc   = (const float*)d_in[11];
    const float* w_proj = (const float*)d_in[12];
    const float* b_proj = (const float*)d_in[13];
    const float* wa1    = (const float*)d_in[14];
    const float* ba1    = (const float*)d_in[15];
    const float* wa2    = (const float*)d_in[16];
    const float* ba2    = (const float*)d_in[17];
    const float* g3     = (const float*)d_in[18];
    const float* b3     = (const float*)d_in[19];
    const float* g1d    = (const float*)d_in[20];
    const float* b1d    = (const float*)d_in[21];
    const float* gn3    = (const float*)d_in[22];
    const float* bn3    = (const float*)d_in[23];
    const float* w_attn1= (const float*)d_in[24];
    const float* b_attn1= (const float*)d_in[25];
    const int* sci      = (const int*)d_in[26];
    const int* segid    = (const int*)d_in[27];
    const int* cluster  = (const int*)d_in[28];
    const int* fgi      = (const int*)d_in[29];
    float* out = (float*)d_out;

    float* base = nullptr;
    cudaGetSymbolAddress((void**)&base, g_scratch);

    const int MTB  = (ROWS_ + 127) / 128;   // 65
    const int MTBp = NPT_ / 128;            // 64
    const int MT64 = (ROWS_ + 63) / 64;     // 129

    // 0) independent prep: fold weights + CSR build for NS-branch segments
    foldw_kernel<<<dim3(C_, NS_), 128>>>(w_attn1, b_attn1, gn3, bn3,
                                         base + O_WATT, base + O_BATT);
    zero_cnt_kernel<<<(NSEGT_ + 255) / 256, 256>>>();
    cnt_kernel<<<(NS_ * NPT_ + 255) / 256, 256>>>(fgi);
    scan_kernel<<<NS_, 512>>>();
    fill_kernel<<<(NS_ * NPT_ + 255) / 256, 256>>>(fgi);
    // 1) LN1 -> bf16
    ln_kernel<1><<<ROWS_, 128>>>(x, (__nv_bfloat16*)(base + O_LN), ln1_g, ln1_b);
    // 2) QKV = LN1 @ w_in^T + b_in -> bf16 (Q pre-scaled by 0.125)
    gemm_bf16<6><<<dim3((3 * C_) / 64, MTB, 1), 128>>>(
        base + O_LN, w_in, b_in, nullptr, nullptr,
        base + O_QKV, ROWS_, 3 * C_, C_, 0, 0, 0, 0, 0, 0);
    // 3) attention (bf16 in/out, 128 q rows/block)
    attn_mma_kernel<<<dim3((G_ + 127) / 128, B_ * H_), 256>>>();
    // 4) out proj + residual x  -> x1 (f32)
    gemm_bf16<3><<<dim3(C_ / 64, MTB, 1), 128>>>(
        base + O_ATT, w_out, b_out, x, nullptr,
        base + O_X1, ROWS_, C_, C_, 0, 0, 0, 0, 0, 0);
    // 5) LN2 -> bf16
    ln_kernel<1><<<ROWS_, 128>>>(base + O_X1, (__nv_bfloat16*)(base + O_LN), ln2_g, ln2_b);
    // 6) fc + quick_gelu -> HFC bf16
    gemm_bf16<2><<<dim3(4 * C_ / 64, MTB, 1), 128>>>(
        base + O_LN, w_fc, b_fc, nullptr, nullptr,
        base + O_HFC, ROWS_, 4 * C_, C_, 0, 0, 0, 0, 0, 0);
    // 7) proj (K=1536) -> XFFN f32
    gemm_bf16<1><<<dim3(C_ / 64, MTB, 1), 128>>>(
        base + O_HFC, w_proj, b_proj, nullptr, nullptr,
        base + O_XFFN, ROWS_, C_, 4 * C_, 0, 0, 0, 0, 0, 0);
    // 8) adapter in + quick_gelu (SIMT fp32: N=48)
    gemm_nt<2><<<dim3(1, MT64, 1), 256>>>(
        base + O_XFFN, wa1, ba1, nullptr, nullptr,
        base + O_A1, ROWS_, 48, C_);
    // 9) adapter out + combine: x2 = x1 + xffn + 0.5*(a1@wa2^T + ba2) (SIMT: K=48)
    gemm_nt<5><<<dim3(C_ / 64, MT64, 1), 256>>>(
        base + O_A1, wa2, ba2, base + O_X1, base + O_XFFN,
        base + O_X2, ROWS_, C_, 48);
    // 10+11) feat(f32) = x2 minus cls rows, xhat(bf16) = layernorm(feat)
    ln_feat_kernel<<<NPT_, 128>>>();
    // 12) fx = (xhat @ W'^T + b')*mask + feat -> FX bf16, batched over NS
    gemm_bf16<4><<<dim3(C_ / 64, MTBp, NS_), 128>>>(
        base + O_LNB, base + O_WATT, base + O_BATT, base + O_FEAT, mask,
        base + O_FX, NPT_, C_, C_,
        0, (long)C_ * C_, C_, (long)NPT_ * C_ / 2, NPT_, 0);
    // 13) sorted segment max+mean -> t3d (3d branch)
    seg3d_kernel<<<MSEG_, 128>>>(sci, segid);
    // 14) BN stats + apply(gelu) for 3d branch
    bnstats_kernel<<<dim3(C_, 1), 256>>>(base + O_T3D, base + O_MEAN3, base + O_RSTD3, MSEG_, 0);
    bnapply_kernel<<<(int)(((long)MSEG_ * C_ + 255) / 256), 256>>>(
        base + O_T3D, base + O_BN3D, base + O_MEAN3, base + O_RSTD3,
        g3, b3, MSEG_, 0, (long)MSEG_ * C_);
    // 15) CSR gather-reduce: per-(branch,segment) max+mean -> SUM1
    seg1d_kernel<<<dim3(SEG1_, NS_), 128>>>();
    // 16) BN stats + apply(gelu) for 1d branches
    bnstats_kernel<<<dim3(C_, NS_), 256>>>(base + O_SUM1, base + O_MEAN1, base + O_RSTD1,
                                           SEG1_, (long)SEG1_ * C_);
    bnapply_kernel<<<(int)(((long)NSEGT_ * C_ + 255) / 256), 256>>>(
        base + O_SUM1, base + O_BN1D, base + O_MEAN1, base + O_RSTD1,
        g1d, b1d, SEG1_, C_, (long)NSEGT_ * C_);
    // 17) final gather + cosine mix + output (incl. cls rows)
    final_kernel<<<ROWS_, 128>>>(out, cluster, fgi);
}

// round 16
// speedup vs baseline: 1.0324x; 1.0007x over previous
#include <cuda_runtime.h>
#include <cuda_bf16.h>
#include <float.h>
#include <math.h>

// ---------------- problem constants ----------------
namespace cfg {
constexpr int B_ = 8, G_ = 1025, GP_ = 1024, C_ = 384, H_ = 6, DH_ = 64;
constexpr int NS_ = 6, MSEG_ = 1024, SEG1_ = 1536;      // SEG1 = B*GRID
constexpr int NPT_ = B_ * GP_;                          // 8192 points
constexpr int ROWS_ = B_ * G_;                          // 8200 rows incl cls
constexpr int NSEGT_ = NS_ * SEG1_;                     // 9216

// scratch layout (floats; several regions hold bf16 and use half)
constexpr long O_LN   = 0;                              // bf16
constexpr long O_QKV  = O_LN   + (long)ROWS_ * C_;      // bf16
constexpr long O_ATT  = O_QKV  + (long)ROWS_ * 3 * C_;  // bf16
constexpr long O_X1   = O_ATT  + (long)ROWS_ * C_;
constexpr long O_HFC  = O_X1   + (long)ROWS_ * C_;      // bf16
constexpr long O_XFFN = O_HFC  + (long)ROWS_ * 4 * C_;
constexpr long O_A1   = O_XFFN + (long)ROWS_ * C_;
constexpr long O_X2   = O_A1   + (long)ROWS_ * 48;
constexpr long O_FEAT = O_X2   + (long)ROWS_ * C_;
constexpr long O_LNB  = O_FEAT + (long)NPT_ * C_;       // bf16
constexpr long O_FX   = O_LNB  + (long)NPT_ * C_;       // bf16
constexpr long O_T3D  = O_FX   + (long)NS_ * NPT_ * C_ / 2;
constexpr long O_BN3D = O_T3D  + (long)MSEG_ * C_;      // bf16
constexpr long O_MEAN3= O_BN3D + (long)MSEG_ * C_ / 2;
constexpr long O_RSTD3= O_MEAN3+ C_;
constexpr long O_SUM1 = O_RSTD3+ C_;
constexpr long O_BN1D = O_SUM1 + (long)NSEGT_ * C_;     // bf16
constexpr long O_MEAN1= O_BN1D + (long)NSEGT_ * C_ / 2;
constexpr long O_RSTD1= O_MEAN1+ (long)NS_ * C_;
constexpr long O_WATT = O_RSTD1+ (long)NS_ * C_;
constexpr long O_BATT = O_WATT + (long)NS_ * C_ * C_;
constexpr long O_CNT  = O_BATT + (long)NS_ * C_;        // int[NSEGT]
constexpr long O_OFF  = O_CNT  + NSEGT_;                // int[NSEGT]
constexpr long O_CUR  = O_OFF  + NSEGT_;                // int[NSEGT]
constexpr long O_LIST = O_CUR  + NSEGT_;                // int[NS*NPT]
constexpr long TOTAL  = O_LIST + (long)NS_ * NPT_;
}
using namespace cfg;

__device__ __align__(16) float g_scratch[TOTAL];

// ---------------- helpers ----------------
__device__ __forceinline__ unsigned pack_bf16(float lo, float hi) {
    unsigned r;
    asm("cvt.rn.bf16x2.f32 %0, %1, %2;" : "=r"(r) : "f"(hi), "f"(lo));
    return r;
}

__device__ __forceinline__ void mma_bf16(float c[4], const unsigned a[4], const unsigned b[2]) {
    asm volatile(
        "mma.sync.aligned.m16n8k16.row.col.f32.bf16.bf16.f32 "
        "{%0,%1,%2,%3},{%4,%5,%6,%7},{%8,%9},{%0,%1,%2,%3};"
        : "+f"(c[0]), "+f"(c[1]), "+f"(c[2]), "+f"(c[3])
        : "r"(a[0]), "r"(a[1]), "r"(a[2]), "r"(a[3]), "r"(b[0]), "r"(b[1]));
}

// pair-interleave within each group of 8 pairs: (q, q+4) become adjacent words
__device__ __forceinline__ int ilv(int p) {
    return (p & ~7) | (((p & 3) << 1) | ((p >> 2) & 1));
}

// ---------------- LayerNorm (C=384, 128 threads), bf16 output ----
template<int AFFINE>
__global__ void ln_kernel(const float* __restrict__ in, __nv_bfloat16* __restrict__ out,
                          const float* __restrict__ gamma, const float* __restrict__ beta)
{
    long row = blockIdx.x;
    const float* x = in + row * C_;
    __nv_bfloat16* o = out + row * C_;
    int t = threadIdx.x;
    float v0 = x[t], v1 = x[t + 128], v2 = x[t + 256];
    float s = v0 + v1 + v2;
    float q = v0 * v0 + v1 * v1 + v2 * v2;
    __shared__ float sm[8];
    #pragma unroll
    for (int o2 = 16; o2; o2 >>= 1) {
        s += __shfl_xor_sync(0xffffffffu, s, o2);
        q += __shfl_xor_sync(0xffffffffu, q, o2);
    }
    int w = t >> 5;
    if ((t & 31) == 0) { sm[w] = s; sm[4 + w] = q; }
    __syncthreads();
    s = sm[0] + sm[1] + sm[2] + sm[3];
    q = sm[4] + sm[5] + sm[6] + sm[7];
    float mean = s * (1.f / C_);
    float var  = q * (1.f / C_) - mean * mean;
    float rstd = rsqrtf(var + 1e-5f);
    if (AFFINE) {
        o[t]       = __float2bfloat16((v0 - mean) * rstd * gamma[t]       + beta[t]);
        o[t + 128] = __float2bfloat16((v1 - mean) * rstd * gamma[t + 128] + beta[t + 128]);
        o[t + 256] = __float2bfloat16((v2 - mean) * rstd * gamma[t + 256] + beta[t + 256]);
    } else {
        o[t]       = __float2bfloat16((v0 - mean) * rstd);
        o[t + 128] = __float2bfloat16((v1 - mean) * rstd);
        o[t + 256] = __float2bfloat16((v2 - mean) * rstd);
    }
}

// ---- fused: feat(f32) = x2 minus cls rows ; xhat(bf16) = layernorm(feat) ----
__global__ void ln_feat_kernel()
{
    int n = blockIdx.x;
    long row = (long)n + (n >> 10) + 1;
    const float* x = g_scratch + O_X2 + row * C_;
    float* feat = g_scratch + O_FEAT + (long)n * C_;
    __nv_bfloat16* xhat = (__nv_bfloat16*)(g_scratch + O_LNB) + (long)n * C_;
    int t = threadIdx.x;
    float v0 = x[t], v1 = x[t + 128], v2 = x[t + 256];
    float s = v0 + v1 + v2;
    float q = v0 * v0 + v1 * v1 + v2 * v2;
    __shared__ float sm[8];
    #pragma unroll
    for (int o2 = 16; o2; o2 >>= 1) {
        s += __shfl_xor_sync(0xffffffffu, s, o2);
        q += __shfl_xor_sync(0xffffffffu, q, o2);
    }
    int w = t >> 5;
    if ((t & 31) == 0) { sm[w] = s; sm[4 + w] = q; }
    __syncthreads();
    s = sm[0] + sm[1] + sm[2] + sm[3];
    q = sm[4] + sm[5] + sm[6] + sm[7];
    float mean = s * (1.f / C_);
    float var  = q * (1.f / C_) - mean * mean;
    float rstd = rsqrtf(var + 1e-5f);
    feat[t]       = v0; xhat[t]       = __float2bfloat16((v0 - mean) * rstd);
    feat[t + 128] = v1; xhat[t + 128] = __float2bfloat16((v1 - mean) * rstd);
    feat[t + 256] = v2; xhat[t + 256] = __float2bfloat16((v2 - mean) * rstd);
}

// ---- fold LN3 affine into w_attn1: W'[n][k]=W[n][k]*g[k], b' = b + W b3 ----
__global__ void foldw_kernel(const float* __restrict__ w, const float* __restrict__ bw,
                             const float* __restrict__ g, const float* __restrict__ b,
                             float* __restrict__ wout, float* __restrict__ bout)
{
    int n = blockIdx.x, z = blockIdx.y, t = threadIdx.x;
    const float* wr = w + ((long)z * C_ + n) * C_;
    const float* gz = g + (long)z * C_;
    const float* bz = b + (long)z * C_;
    float* wo = wout + ((long)z * C_ + n) * C_;
    float acc = 0.f;
    for (int c = t; c < C_; c += 128) {
        float wv = wr[c];
        wo[c] = wv * gz[c];
        acc += wv * bz[c];
    }
    #pragma unroll
    for (int o2 = 16; o2; o2 >>= 1) acc += __shfl_xor_sync(0xffffffffu, acc, o2);
    __shared__ float sr[4];
    if ((t & 31) == 0) sr[t >> 5] = acc;
    __syncthreads();
    if (t == 0) bout[(long)z * C_ + n] = sr[0] + sr[1] + sr[2] + sr[3] + bw[(long)z * C_ + n];
}

// ---------------- BF16 tensor-core NT GEMM: C[m,n] = sum_k A[m,k]*W[n,k] -----
// A operand is bf16 in gmem (uint pairs); W is f32 (packed in sts).
// MODE 1: +bias ; 2: quick_gelu(+bias) -> bf16 out ; 3: +bias + R1 ;
// MODE 4: (+bias)*mrow[m]+R1 -> bf16 out ; 6: bf16 out, Q cols pre-scaled 0.125
template<int MODE>
__global__ void __launch_bounds__(128) gemm_bf16(
    const void* __restrict__ Av, const float* __restrict__ W,
    const float* __restrict__ bias, const float* __restrict__ R1,
    const float* __restrict__ mrow, float* __restrict__ Co,
    int Mr, int Nc, int K,
    long aZ, long wZ, long bZ, long cZ, long mZ, long r1Z)
{
    constexpr int BM = 128, BN = 64, BK = 16, LD = 12;   // LD in uint32 (bf16 pairs)
    __shared__ unsigned As[2][BM * LD];
    __shared__ unsigned Bs[2][BN * LD];
    int z = blockIdx.z;
    const unsigned* A = (const unsigned*)Av + (long)z * aZ;   // aZ in uints
    const int KW = K / 2;                                      // uints per A row
    W += (long)z * wZ; bias += (long)z * bZ; Co += (long)z * cZ;
    if (MODE == 4) mrow += (long)z * mZ;
    if (MODE == 3 || MODE == 4) R1 += (long)z * r1Z;
    int m0 = blockIdx.y * BM, n0 = blockIdx.x * BN;
    int tid = threadIdx.x;

    int arow = tid >> 2;            // 0..31
    int c4 = tid & 3;               // float4 index within the 16-k stage
    int acol = c4 * 4;
    int p0 = (c4 < 2) ? 4 * c4 : 4 * c4 - 7;    // interleaved pair position

    const unsigned* Ap[4]; bool am[4];
    #pragma unroll
    for (int i = 0; i < 4; i++) {
        int gm = m0 + arow + 32 * i;
        am[i] = gm < Mr;
        Ap[i] = A + (long)gm * KW + c4 * 2;
    }
    const float* Wp0 = W + (long)(n0 + arow) * K + acol;
    const float* Wp1 = W + (long)(n0 + arow + 32) * K + acol;

    uint2 ua[4]; float4 lb[2];
    auto ldg = [&](int k0) {
        int kw = k0 / 2;
        #pragma unroll
        for (int i = 0; i < 4; i++)
            ua[i] = am[i] ? *(const uint2*)(Ap[i] + kw) : make_uint2(0, 0);
        lb[0] = *(const float4*)(Wp0 + k0);
        lb[1] = *(const float4*)(Wp1 + k0);
    };
    auto sts = [&](int buf) {
        #pragma unroll
        for (int i = 0; i < 4; i++) {
            unsigned* p = &As[buf][(arow + 32 * i) * LD + p0];
            p[0] = ua[i].x;
            p[2] = ua[i].y;
        }
        #pragma unroll
        for (int j = 0; j < 2; j++) {
            unsigned* p = &Bs[buf][(arow + 32 * j) * LD + p0];
            p[0] = pack_bf16(lb[j].x, lb[j].y);
            p[2] = pack_bf16(lb[j].z, lb[j].w);
        }
    };

    int warp = tid >> 5, lane = tid & 31;
    int wm = (warp >> 1) * 64, wn = (warp & 1) * 32;
    int g = lane >> 2, r = lane & 3;

    float acc[4][4][4] = {};

    ldg(0);
    sts(0);
    __syncthreads();

    const int nstage = K / BK;
    int buf = 0;
    for (int s = 0; s < nstage; s++) {
        if (s + 1 < nstage) ldg((s + 1) * BK);
        unsigned af[4][4], bf[4][2];
        #pragma unroll
        for (int i = 0; i < 4; i++) {
            int mr_ = wm + 16 * i + g;
            uint2 va = *(const uint2*)&As[buf][mr_ * LD + 2 * r];
            uint2 vb = *(const uint2*)&As[buf][(mr_ + 8) * LD + 2 * r];
            af[i][0] = va.x; af[i][2] = va.y;
            af[i][1] = vb.x; af[i][3] = vb.y;
        }
        #pragma unroll
        for (int j = 0; j < 4; j++) {
            uint2 w2 = *(const uint2*)&Bs[buf][(wn + 8 * j + g) * LD + 2 * r];
            bf[j][0] = w2.x; bf[j][1] = w2.y;
        }
        #pragma unroll
        for (int i = 0; i < 4; i++)
            #pragma unroll
            for (int j = 0; j < 4; j++)
                mma_bf16(acc[i][j], af[i], bf[j]);
        if (s + 1 < nstage) sts(buf ^ 1);
        __syncthreads();
        buf ^= 1;
    }

    // epilogue
    __nv_bfloat16* CoH = (__nv_bfloat16*)Co;
    #pragma unroll
    for (int i = 0; i < 4; i++) {
        #pragma unroll
        for (int half = 0; half < 2; half++) {
            int m = m0 + wm + 16 * i + g + 8 * half;
            if (m >= Mr) continue;
            float msk = (MODE == 4) ? mrow[m] : 0.f;
            #pragma unroll
            for (int j = 0; j < 4; j++) {
                int n = n0 + wn + 8 * j + 2 * r;
                float v0 = acc[i][j][2 * half]     + bias[n];
                float v1 = acc[i][j][2 * half + 1] + bias[n + 1];
                long idx = (long)m * Nc + n;
                if (MODE == 6) {
                    float sc = (n < C_) ? 0.125f : 1.f;
                    *(unsigned*)(CoH + idx) = pack_bf16(v0 * sc, v1 * sc);
                    continue;
                }
                if (MODE == 2) {
                    *(unsigned*)(CoH + idx) = pack_bf16(
                        v0 / (1.f + __expf(-1.702f * v0)),
                        v1 / (1.f + __expf(-1.702f * v1)));
                    continue;
                }
                if (MODE == 4) {
                    float fx0 = v0 * msk + R1[idx];
                    float fx1 = v1 * msk + R1[idx + 1];
                    *(unsigned*)(CoH + idx) = pack_bf16(fx0, fx1);
                    continue;
                }
                float r0, r1v;
                if (MODE == 1)      { r0 = v0; r1v = v1; }
                else                { r0 = v0 + R1[idx]; r1v = v1 + R1[idx + 1]; }
                *(float2*)(Co + idx) = make_float2(r0, r1v);
            }
        }
    }
}

// ---------------- SIMT fallback GEMM (adapter shapes, f32) ----------------
// MODE 2: quick_gelu(+bias) ; 5: R1 + R2 + 0.5*(+bias)
template<int MODE>
__global__ void __launch_bounds__(256) gemm_nt(
    const float* __restrict__ A, const float* __restrict__ W,
    const float* __restrict__ bias, const float* __restrict__ R1,
    const float* __restrict__ R2, float* __restrict__ Co,
    int Mr, int Nc, int K)
{
    __shared__ float As[16][64];
    __shared__ float Ws[16][64];
    int m0 = blockIdx.y * 64, n0 = blockIdx.x * 64;
    int tid = threadIdx.x;
    int lr = tid >> 2, lk = (tid & 3) << 2;
    int ty = tid >> 4, tx = tid & 15;
    float acc[4][4] = {};
    for (int k0 = 0; k0 < K; k0 += 16) {
        float4 va = make_float4(0, 0, 0, 0), vw = make_float4(0, 0, 0, 0);
        int gm = m0 + lr;
        if (gm < Mr) va = *(const float4*)(A + (long)gm * K + (k0 + lk));
        int gn = n0 + lr;
        if (gn < Nc) vw = *(const float4*)(W + (long)gn * K + (k0 + lk));
        __syncthreads();
        As[lk][lr] = va.x; As[lk + 1][lr] = va.y; As[lk + 2][lr] = va.z; As[lk + 3][lr] = va.w;
        Ws[lk][lr] = vw.x; Ws[lk + 1][lr] = vw.y; Ws[lk + 2][lr] = vw.z; Ws[lk + 3][lr] = vw.w;
        __syncthreads();
        #pragma unroll
        for (int kk = 0; kk < 16; kk++) {
            float4 a4 = *(const float4*)&As[kk][ty << 2];
            float4 b4 = *(const float4*)&Ws[kk][tx << 2];
            acc[0][0] += a4.x * b4.x; acc[0][1] += a4.x * b4.y; acc[0][2] += a4.x * b4.z; acc[0][3] += a4.x * b4.w;
            acc[1][0] += a4.y * b4.x; acc[1][1] += a4.y * b4.y; acc[1][2] += a4.y * b4.z; acc[1][3] += a4.y * b4.w;
            acc[2][0] += a4.z * b4.x; acc[2][1] += a4.z * b4.y; acc[2][2] += a4.z * b4.z; acc[2][3] += a4.z * b4.w;
            acc[3][0] += a4.w * b4.x; acc[3][1] += a4.w * b4.y; acc[3][2] += a4.w * b4.z; acc[3][3] += a4.w * b4.w;
        }
    }
    #pragma unroll
    for (int i = 0; i < 4; i++) {
        int m = m0 + (ty << 2) + i;
        if (m >= Mr) continue;
        #pragma unroll
        for (int j = 0; j < 4; j++) {
            int n = n0 + (tx << 2) + j;
            if (n >= Nc) continue;
            float v = acc[i][j] + bias[n];
            long idx = (long)m * Nc + n;
            float rr;
            if (MODE == 2) rr = v / (1.f + __expf(-1.702f * v));
            else           rr = R1[idx] + R2[idx] + 0.5f * v;
            Co[idx] = rr;
        }
    }
}

// ---------------- bf16 tensor-core flash attention ----------------
// 128 q-rows per block (8 warps x m16), 64-key tiles, dh=64.
__global__ void __launch_bounds__(256, 2) attn_mma_kernel()
{
    constexpr int LDK = 36, LDVT = 36;   // words (bf16 pairs), 32 + pad
    __shared__ unsigned Ks[64 * LDK];
    __shared__ unsigned Vt[64 * LDVT];
    const unsigned* qkv = (const unsigned*)(g_scratch + O_QKV);
    const int RW = 3 * C_ / 2;
    __nv_bfloat16* attH = (__nv_bfloat16*)(g_scratch + O_ATT);
    int bh = blockIdx.y;
    int b = bh / H_, h = bh % H_;
    int q0 = blockIdx.x * 128;
    const unsigned* qb = qkv + (long)b * G_ * RW + h * (DH_ / 2);
    const unsigned* kb = qb + C_ / 2;
    const unsigned* vb = qb + C_;
    int tid = threadIdx.x, warp = tid >> 5, lane = tid & 31;
    int g = lane >> 2, r = lane & 3;

    unsigned qf[4][4];
    int qrow0 = q0 + warp * 16 + g;
    int qrow1 = qrow0 + 8;
    bool qv0 = qrow0 < G_, qv1 = qrow1 < G_;
    const unsigned* qp0 = qb + (long)qrow0 * RW;
    const unsigned* qp1 = qb + (long)qrow1 * RW;
    #pragma unroll
    for (int kbq = 0; kbq < 4; kbq++) {
        int u0 = kbq * 8 + r;
        qf[kbq][0] = qv0 ? qp0[u0]     : 0u;
        qf[kbq][1] = qv1 ? qp1[u0]     : 0u;
        qf[kbq][2] = qv0 ? qp0[u0 + 4] : 0u;
        qf[kbq][3] = qv1 ? qp1[u0 + 4] : 0u;
    }

    float o[8][4] = {};
    float m0v = -FLT_MAX, m1v = -FLT_MAX, l0 = 0.f, l1 = 0.f;
    unsigned short* VtS = (unsigned short*)Vt;

    for (int n0 = 0; n0 < G_; n0 += 64) {
        __syncthreads();
        #pragma unroll
        for (int it = 0; it < 4; it++) {
            int i = tid + it * 256;
            int key = i >> 4, c4 = i & 15;
            int gk = n0 + key;
            uint2 kv = make_uint2(0, 0), vv = make_uint2(0, 0);
            if (gk < G_) {
                kv = *(const uint2*)(kb + (long)gk * RW + c4 * 2);
                vv = *(const uint2*)(vb + (long)gk * RW + c4 * 2);
            }
            Ks[key * LDK + ilv(2 * c4)]     = kv.x;
            Ks[key * LDK + ilv(2 * c4 + 1)] = kv.y;
            int vword = ilv(key >> 1);
            int vhalf = key & 1;
            VtS[((4 * c4 + 0) * LDVT + vword) * 2 + vhalf] = (unsigned short)(vv.x & 0xffffu);
            VtS[((4 * c4 + 1) * LDVT + vword) * 2 + vhalf] = (unsigned short)(vv.x >> 16);
            VtS[((4 * c4 + 2) * LDVT + vword) * 2 + vhalf] = (unsigned short)(vv.y & 0xffffu);
            VtS[((4 * c4 + 3) * LDVT + vword) * 2 + vhalf] = (unsigned short)(vv.y >> 16);
        }
        __syncthreads();

        float s[8][4] = {};
        #pragma unroll
        for (int kbq = 0; kbq < 4; kbq++) {
            #pragma unroll
            for (int j = 0; j < 8; j++) {
                uint2 bv = *(const uint2*)&Ks[(j * 8 + g) * LDK + kbq * 8 + 2 * r];
                unsigned bfr[2] = {bv.x, bv.y};
                mma_bf16(s[j], qf[kbq], bfr);
            }
        }
        float mx0 = -FLT_MAX, mx1 = -FLT_MAX;
        #pragma unroll
        for (int j = 0; j < 8; j++) {
            int c = n0 + j * 8 + 2 * r;
            if (c >= G_)     { s[j][0] = -FLT_MAX; s[j][2] = -FLT_MAX; }
            if (c + 1 >= G_) { s[j][1] = -FLT_MAX; s[j][3] = -FLT_MAX; }
            mx0 = fmaxf(mx0, fmaxf(s[j][0], s[j][1]));
            mx1 = fmaxf(mx1, fmaxf(s[j][2], s[j][3]));
        }
        mx0 = fmaxf(mx0, __shfl_xor_sync(0xffffffffu, mx0, 1));
        mx0 = fmaxf(mx0, __shfl_xor_sync(0xffffffffu, mx0, 2));
        mx1 = fmaxf(mx1, __shfl_xor_sync(0xffffffffu, mx1, 1));
        mx1 = fmaxf(mx1, __shfl_xor_sync(0xffffffffu, mx1, 2));
        float mn0 = fmaxf(m0v, mx0), mn1 = fmaxf(m1v, mx1);
        float a0 = __expf(m0v - mn0), a1 = __expf(m1v - mn1);
        m0v = mn0; m1v = mn1;
        #pragma unroll
        for (int j = 0; j < 8; j++) {
            o[j][0] *= a0; o[j][1] *= a0; o[j][2] *= a1; o[j][3] *= a1;
        }

        float ps0 = 0.f, ps1 = 0.f;
        #pragma unroll
        for (int j = 0; j < 8; j++) {
            s[j][0] = __expf(s[j][0] - mn0);
            s[j][1] = __expf(s[j][1] - mn0);
            s[j][2] = __expf(s[j][2] - mn1);
            s[j][3] = __expf(s[j][3] - mn1);
            ps0 += s[j][0] + s[j][1];
            ps1 += s[j][2] + s[j][3];
        }
        ps0 += __shfl_xor_sync(0xffffffffu, ps0, 1);
        ps0 += __shfl_xor_sync(0xffffffffu, ps0, 2);
        ps1 += __shfl_xor_sync(0xffffffffu, ps1, 1);
        ps1 += __shfl_xor_sync(0xffffffffu, ps1, 2);
        l0 = l0 * a0 + ps0;
        l1 = l1 * a1 + ps1;

        #pragma unroll
        for (int kbq = 0; kbq < 4; kbq++) {
            unsigned af[4];
            af[0] = pack_bf16(s[2 * kbq][0],     s[2 * kbq][1]);
            af[1] = pack_bf16(s[2 * kbq][2],     s[2 * kbq][3]);
            af[2] = pack_bf16(s[2 * kbq + 1][0], s[2 * kbq + 1][1]);
            af[3] = pack_bf16(s[2 * kbq + 1][2], s[2 * kbq + 1][3]);
            #pragma unroll
            for (int j = 0; j < 8; j++) {
                uint2 vv = *(const uint2*)&Vt[(j * 8 + g) * LDVT + kbq * 8 + 2 * r];
                unsigned bfr[2] = {vv.x, vv.y};
                mma_bf16(o[j], af, bfr);
            }
        }
    }

    float inv0 = qv0 ? 1.f / l0 : 0.f;
    float inv1 = qv1 ? 1.f / l1 : 0.f;
    #pragma unroll
    for (int j = 0; j < 8; j++) {
        int c = h * DH_ + j * 8 + 2 * r;
        if (qv0) *(unsigned*)&attH[((long)b * G_ + qrow0) * C_ + c] =
            pack_bf16(o[j][0] * inv0, o[j][1] * inv0);
        if (qv1) *(unsigned*)&attH[((long)b * G_ + qrow1) * C_ + c] =
            pack_bf16(o[j][2] * inv1, o[j][3] * inv1);
    }
}

// ---------------- sorted-segment max+mean (M=1024 segments) ------------------
__global__ void seg3d_kernel(const int* __restrict__ sci, const int* __restrict__ segid)
{
    const float* feat = g_scratch + O_FEAT;
    float* t3 = g_scratch + O_T3D;
    int s = blockIdx.x;
    __shared__ int sh[2];
    if (threadIdx.x < 2) {
        int target = s + threadIdx.x;
        int lo = 0, hi = NPT_;
        while (lo < hi) { int mid = (lo + hi) >> 1; if (segid[mid] < target) lo = mid + 1; else hi = mid; }
        sh[threadIdx.x] = lo;
    }
    __syncthreads();
    int lo = sh[0], hi = sh[1];
    int t = threadIdx.x;
    float mx[3] = {-FLT_MAX, -FLT_MAX, -FLT_MAX};
    float sm[3] = {0, 0, 0};
    for (int r = lo; r < hi; r++) {
        int n = sci[r];
        const float* f = feat + (long)n * C_;
        #pragma unroll
        for (int j = 0; j < 3; j++) {
            float v = f[t + j * 128];
            mx[j] = fmaxf(mx[j], v);
            sm[j] += v;
        }
    }
    float cnt = (float)(hi - lo);
    float invc = 1.f / fmaxf(cnt, 1.f);
    #pragma unroll
    for (int j = 0; j < 3; j++) {
        float m_ = (hi > lo) ? mx[j] : 0.f;
        t3[(long)s * C_ + t + j * 128] = m_ + sm[j] * invc;
    }
}

// ---------------- CSR build for NS x 1536 segments ----------------
__global__ void zero_cnt_kernel()
{
    int i = blockIdx.x * 256 + threadIdx.x;
    if (i < NSEGT_) ((int*)(g_scratch + O_CNT))[i] = 0;
}

__global__ void cnt_kernel(const int* __restrict__ fgi)
{
    int i = blockIdx.x * 256 + threadIdx.x;
    if (i < NS_ * NPT_)
        atomicAdd((int*)(g_scratch + O_CNT) + (long)(i / NPT_) * SEG1_ + fgi[i], 1);
}

// per-branch exclusive scan: grid = NS_, 512 threads x 3 entries (SEG1_ = 1536)
__global__ void __launch_bounds__(512) scan_kernel()
{
    int z = blockIdx.x, t = threadIdx.x;
    const int* cnt = (const int*)(g_scratch + O_CNT) + (long)z * SEG1_;
    int* off = (int*)(g_scratch + O_OFF) + (long)z * SEG1_;
    int* cur = (int*)(g_scratch + O_CUR) + (long)z * SEG1_;
    int base = t * 3;
    int v0 = cnt[base], v1 = cnt[base + 1], v2 = cnt[base + 2];
    int tot = v0 + v1 + v2;
    int lane = t & 31, warp = t >> 5;    // 16 warps
    int inc = tot;
    #pragma unroll
    for (int o2 = 1; o2 < 32; o2 <<= 1) {
        int x = __shfl_up_sync(0xffffffffu, inc, o2);
        if (lane >= o2) inc += x;
    }
    __shared__ int ws[16];
    if (lane == 31) ws[warp] = inc;
    __syncthreads();
    if (warp == 0) {
        int wv = (lane < 16) ? ws[lane] : 0;
        int wi = wv;
        #pragma unroll
        for (int o2 = 1; o2 < 16; o2 <<= 1) {
            int x = __shfl_up_sync(0xffffffffu, wi, o2);
            if (lane >= o2) wi += x;
        }
        if (lane < 16) ws[lane] = wi - wv;
    }
    __syncthreads();
    int offv = z * NPT_ + ws[warp] + (inc - tot);
    off[base] = offv;     cur[base] = offv;     offv += v0;
    off[base + 1] = offv; cur[base + 1] = offv; offv += v1;
    off[base + 2] = offv; cur[base + 2] = offv;
}

__global__ void fill_kernel(const int* __restrict__ fgi)
{
    int i = blockIdx.x * 256 + threadIdx.x;
    if (i >= NS_ * NPT_) return;
    int s = i / NPT_, n = i - s * NPT_;
    int g = fgi[i];
    int pos = atomicAdd((int*)(g_scratch + O_CUR) + (long)s * SEG1_ + g, 1);
    ((int*)(g_scratch + O_LIST))[pos] = n;
}

// ---- gather-reduce (bf16 FX): SUM1[z,seg,:] = max + mean over segment rows ----
__global__ void seg1d_kernel()
{
    int seg = blockIdx.x, z = blockIdx.y;
    long idx = (long)z * SEG1_ + seg;
    int lo = ((const int*)(g_scratch + O_OFF))[idx];
    int cnt = ((const int*)(g_scratch + O_CNT))[idx];
    const int* list = (const int*)(g_scratch + O_LIST);
    const __nv_bfloat16* fx = (const __nv_bfloat16*)(g_scratch + O_FX) + (long)z * NPT_ * C_;
    int t = threadIdx.x;
    float mx[3] = {-FLT_MAX, -FLT_MAX, -FLT_MAX};
    float sm[3] = {0, 0, 0};
    for (int r = 0; r < cnt; r++) {
        const __nv_bfloat16* f = fx + (long)list[lo + r] * C_;
        #pragma unroll
        for (int j = 0; j < 3; j++) {
            float v = __bfloat162float(f[t + j * 128]);
            mx[j] = fmaxf(mx[j], v);
            sm[j] += v;
        }
    }
    float invc = 1.f / fmaxf((float)cnt, 1.f);
    float* o = g_scratch + O_SUM1 + idx * C_;
    #pragma unroll
    for (int j = 0; j < 3; j++) {
        float m_ = (cnt > 0) ? mx[j] : 0.f;
        o[t + j * 128] = m_ + sm[j] * invc;
    }
}

// ---------------- batchnorm stats (per column over rows) ----------------
__global__ void bnstats_kernel(const float* __restrict__ in, float* __restrict__ mean,
                               float* __restrict__ rstd, int rows, long inZ)
{
    int c = blockIdx.x, z = blockIdx.y;
    in += (long)z * inZ;
    float s = 0.f, q = 0.f;
    for (int r = threadIdx.x; r < rows; r += blockDim.x) {
        float v = in[(long)r * C_ + c];
        s += v; q += v * v;
    }
    #pragma unroll
    for (int o2 = 16; o2; o2 >>= 1) {
        s += __shfl_xor_sync(0xffffffffu, s, o2);
        q += __shfl_xor_sync(0xffffffffu, q, o2);
    }
    __shared__ float ss[8], qq[8];
    int w = threadIdx.x >> 5;
    if ((threadIdx.x & 31) == 0) { ss[w] = s; qq[w] = q; }
    __syncthreads();
    if (threadIdx.x == 0) {
        float S = 0.f, Q = 0.f;
        #pragma unroll
        for (int i = 0; i < 8; i++) { S += ss[i]; Q += qq[i]; }
        float m = S / rows;
        float var = Q / rows - m * m;
        mean[(long)z * C_ + c] = m;
        rstd[(long)z * C_ + c] = rsqrtf(var + 1e-5f);
    }
}

// ---------------- batchnorm apply + exact GELU -> bf16 output ----------------
__global__ void bnapply_kernel(const float* __restrict__ in, __nv_bfloat16* __restrict__ out,
                               const float* __restrict__ mean, const float* __restrict__ rstd,
                               const float* __restrict__ gamma, const float* __restrict__ beta,
                               int rows, long gZ, long total)
{
    long i = blockIdx.x * (long)blockDim.x + threadIdx.x;
    if (i >= total) return;
    long rz = i / C_;
    int c = (int)(i - rz * C_);
    int z = (int)(rz / rows);
    float v = (in[i] - mean[(long)z * C_ + c]) * rstd[(long)z * C_ + c] * gamma[z * gZ + c] + beta[z * gZ + c];
    out[i] = __float2bfloat16(v * normcdff(v));
}

// ---------------- final: gather (bf16), cosine weights, mix, write output ----
__global__ void final_kernel(float* __restrict__ out,
                             const int* __restrict__ cluster, const int* __restrict__ fgi)
{
    int n = blockIdx.x;
    int t = threadIdx.x;
    if (n >= NPT_) {                    // cls rows
        int b = n - NPT_;
        #pragma unroll
        for (int j = 0; j < 3; j++)
            out[(long)b * G_ * C_ + t + j * 128] = g_scratch[O_X2 + (long)b * G_ * C_ + t + j * 128];
        return;
    }
    __shared__ float sm[4];
    auto bsum = [&](float v) -> float {
        #pragma unroll
        for (int o2 = 16; o2; o2 >>= 1) v += __shfl_xor_sync(0xffffffffu, v, o2);
        int w = t >> 5;
        if ((t & 31) == 0) sm[w] = v;
        __syncthreads();
        float r = sm[0] + sm[1] + sm[2] + sm[3];
        __syncthreads();
        return r;
    };
    float r3[3];
    const __nv_bfloat16* p3 = (const __nv_bfloat16*)(g_scratch + O_BN3D) + (long)cluster[n] * C_;
    float pn3 = 0.f;
    #pragma unroll
    for (int j = 0; j < 3; j++) {
        r3[j] = __bfloat162float(p3[t + j * 128]);
        pn3 += r3[j] * r3[j];
    }
    float n3sq = bsum(pn3);
    float na = fmaxf(sqrtf(n3sq), 1e-8f);

    float rs[6][3];
    float wts[6];
    float wsum = 0.f;
    const __nv_bfloat16* bn1 = (const __nv_bfloat16*)(g_scratch + O_BN1D);
    for (int s = 0; s < NS_; s++) {
        const __nv_bfloat16* ps = bn1 + ((long)s * SEG1_ + fgi[(long)s * NPT_ + n]) * C_;
        float pd = 0.f, pq = 0.f;
        #pragma unroll
        for (int j = 0; j < 3; j++) {
            float v = __bfloat162float(ps[t + j * 128]);
            rs[s][j] = v;
            pd += v * r3[j];
            pq += v * v;
        }
        float dot = bsum(pd);
        float nq = bsum(pq);
        float nb = fmaxf(sqrtf(nq), 1e-8f);
        float sim = dot / (na * nb);
        wts[s] = (sim + 1.f) * 0.5f;
        wsum += wts[s];
    }
    float invw = 1.f / wsum;
    long orow = (long)n + (n >> 10) + 1;
    #pragma unroll
    for (int j = 0; j < 3; j++) {
        int c = t + j * 128;
        float acc = 0.f;
        #pragma unroll
        for (int s = 0; s < NS_; s++) acc += rs[s][j] * wts[s];
        out[orow * C_ + c] = g_scratch[O_FEAT + (long)n * C_ + c] + 0.3f * acc * invw;
    }
}

// ---------------- host launch ----------------
extern "C" void kernel_launch(void* const* d_in, const int* in_sizes, int n_in,
                              void* d_out, int out_size)
{
    const float* x      = (const float*)d_in[0];
    const float* mask   = (const float*)d_in[1];
    const float* ln1_g  = (const float*)d_in[2];
    const float* ln1_b  = (const float*)d_in[3];
    const float* ln2_g  = (const float*)d_in[4];
    const float* ln2_b  = (const float*)d_in[5];
    const float* w_in   = (const float*)d_in[6];
    const float* b_in   = (const float*)d_in[7];
    const float* w_out  = (const float*)d_in[8];
    const float* b_out  = (const float*)d_in[9];
    const float* w_fc   = (const float*)d_in[10];
    const float* b_fc   = (const float*)d_in[11];
    const float* w_proj = (const float*)d_in[12];
    const float* b_proj = (const float*)d_in[13];
    const float* wa1    = (const float*)d_in[14];
    const float* ba1    = (const float*)d_in[15];
    const float* wa2    = (const float*)d_in[16];
    const float* ba2    = (const float*)d_in[17];
    const float* g3     = (const float*)d_in[18];
    const float* b3     = (const float*)d_in[19];
    const float* g1d    = (const float*)d_in[20];
    const float* b1d    = (const float*)d_in[21];
    const float* gn3    = (const float*)d_in[22];
    const float* bn3    = (const float*)d_in[23];
    const float* w_attn1= (const float*)d_in[24];
    const float* b_attn1= (const float*)d_in[25];
    const int* sci      = (const int*)d_in[26];
    const int* segid    = (const int*)d_in[27];
    const int* cluster  = (const int*)d_in[28];
    const int* fgi      = (const int*)d_in[29];
    float* out = (float*)d_out;

    float* base = nullptr;
    cudaGetSymbolAddress((void**)&base, g_scratch);

    const int MTB  = (ROWS_ + 127) / 128;   // 65
    const int MTBp = NPT_ / 128;            // 64
    const int MT64 = (ROWS_ + 63) / 64;     // 129

    // 0) independent prep: fold weights + CSR build for NS-branch segments
    foldw_kernel<<<dim3(C_, NS_), 128>>>(w_attn1, b_attn1, gn3, bn3,
                                         base + O_WATT, base + O_BATT);
    zero_cnt_kernel<<<(NSEGT_ + 255) / 256, 256>>>();
    cnt_kernel<<<(NS_ * NPT_ + 255) / 256, 256>>>(fgi);
    scan_kernel<<<NS_, 512>>>();
    fill_kernel<<<(NS_ * NPT_ + 255) / 256, 256>>>(fgi);
    // 1) LN1 -> bf16
    ln_kernel<1><<<ROWS_, 128>>>(x, (__nv_bfloat16*)(base + O_LN), ln1_g, ln1_b);
    // 2) QKV = LN1 @ w_in^T + b_in -> bf16 (Q pre-scaled by 0.125)
    gemm_bf16<6><<<dim3((3 * C_) / 64, MTB, 1), 128>>>(
        base + O_LN, w_in, b_in, nullptr, nullptr,
        base + O_QKV, ROWS_, 3 * C_, C_, 0, 0, 0, 0, 0, 0);
    // 3) attention (bf16 in/out, 128 q rows/block)
    attn_mma_kernel<<<dim3((G_ + 127) / 128, B_ * H_), 256>>>();
    // 4) out proj + residual x  -> x1 (f32)
    gemm_bf16<3><<<dim3(C_ / 64, MTB, 1), 128>>>(
        base + O_ATT, w_out, b_out, x, nullptr,
        base + O_X1, ROWS_, C_, C_, 0, 0, 0, 0, 0, 0);
    // 5) LN2 -> bf16
    ln_kernel<1><<<ROWS_, 128>>>(base + O_X1, (__nv_bfloat16*)(base + O_LN), ln2_g, ln2_b);
    // 6) fc + quick_gelu -> HFC bf16
    gemm_bf16<2><<<dim3(4 * C_ / 64, MTB, 1), 128>>>(
        base + O_LN, w_fc, b_fc, nullptr, nullptr,
        base + O_HFC, ROWS_, 4 * C_, C_, 0, 0, 0, 0, 0, 0);
    // 7) proj (K=1536) -> XFFN f32
    gemm_bf16<1><<<dim3(C_ / 64, MTB, 1), 128>>>(
        base + O_HFC, w_proj, b_proj, nullptr, nullptr,
        base + O_XFFN, ROWS_, C_, 4 * C_, 0, 0, 0, 0, 0, 0);
    // 8) adapter in + quick_gelu (SIMT fp32: N=48)
    gemm_nt<2><<<dim3(1, MT64, 1), 256>>>(
        base + O_XFFN, wa1, ba1, nullptr, nullptr,
        base + O_A1, ROWS_, 48, C_);
    // 9) adapter out + combine: x2 = x1 + xffn + 0.5*(a1@wa2^T + ba2) (SIMT: K=48)
    gemm_nt<5><<<dim3(C_ / 64, MT64, 1), 256>>>(
        base + O_A1, wa2, ba2, base + O_X1, base + O_XFFN,
        base + O_X2, ROWS_, C_, 48);
    // 10+11) feat(f32) = x2 minus cls rows, xhat(bf16) = layernorm(feat)
    ln_feat_kernel<<<NPT_, 128>>>();
    // 12) fx = (xhat @ W'^T + b')*mask + feat -> FX bf16, batched over NS
    gemm_bf16<4><<<dim3(C_ / 64, MTBp, NS_), 128>>>(
        base + O_LNB, base + O_WATT, base + O_BATT, base + O_FEAT, mask,
        base + O_FX, NPT_, C_, C_,
        0, (long)C_ * C_, C_, (long)NPT_ * C_ / 2, NPT_, 0);
    // 13) sorted segment max+mean -> t3d (3d branch)
    seg3d_kernel<<<MSEG_, 128>>>(sci, segid);
    // 14) BN stats + apply(gelu) for 3d branch -> BN3D bf16
    bnstats_kernel<<<dim3(C_, 1), 256>>>(base + O_T3D, base + O_MEAN3, base + O_RSTD3, MSEG_, 0);
    bnapply_kernel<<<(int)(((long)MSEG_ * C_ + 255) / 256), 256>>>(
        base + O_T3D, (__nv_bfloat16*)(base + O_BN3D), base + O_MEAN3, base + O_RSTD3,
        g3, b3, MSEG_, 0, (long)MSEG_ * C_);
    // 15) CSR gather-reduce: per-(branch,segment) max+mean -> SUM1
    seg1d_kernel<<<dim3(SEG1_, NS_), 128>>>();
    // 16) BN stats + apply(gelu) for 1d branches -> BN1D bf16
    bnstats_kernel<<<dim3(C_, NS_), 256>>>(base + O_SUM1, base + O_MEAN1, base + O_RSTD1,
                                           SEG1_, (long)SEG1_ * C_);
    bnapply_kernel<<<(int)(((long)NSEGT_ * C_ + 255) / 256), 256>>>(
        base + O_SUM1, (__nv_bfloat16*)(base + O_BN1D), base + O_MEAN1, base + O_RSTD1,
        g1d, b1d, SEG1_, C_, (long)NSEGT_ * C_);
    // 17) final gather (bf16) + cosine mix + output (incl. cls rows)
    final_kernel<<<ROWS_, 128>>>(out, cluster, fgi);
}